// round 12
// baseline (speedup 1.0000x reference)
#include <cuda_runtime.h>
#include <cuda_bf16.h>
#include <cstdint>

#define NN 12288
#define EE 393216
#define SM_STRIDE 72   // bf16 elems per row (144B; 144 mod 128 = 16 -> conflict-free)
#define T_STRIDE 132   // fp32 transpose staging stride (128+4)

// ---------------- scratch (static device globals; no allocation) ----------------
static __device__ float g_tmp[NN * 256];
static __device__ float g_h1 [NN * 128];
static __device__ float g_a  [NN * 128];
static __device__ __nv_bfloat16 g_s_hi[NN * 64];
static __device__ __nv_bfloat16 g_s_lo[NN * 64];

static __device__ int   g_cnt[NN];
static __device__ int   g_cur[NN];
static __device__ int   g_off[NN + 1];
static __device__ int   g_csr_src[EE];
static __device__ float g_csr_norm[EE];
static __device__ float g_dinv_sqrt[NN];
static __device__ float g_deg_inv[NN];

// ---------------- CSR construction ----------------
__global__ void k_init() {
    int i = blockIdx.x * blockDim.x + threadIdx.x;
    if (i < NN) g_cnt[i] = 0;
}

// edge_index is int32 on device (JAX x64 disabled downcasts jnp.int64).
__global__ void k_count(const int* __restrict__ ei) {
    int e = blockIdx.x * blockDim.x + threadIdx.x;
    if (e < EE) {
        int d = ei[EE + e];
        if (d >= 0 && d < NN) atomicAdd(&g_cnt[d], 1);
    }
}

// fused: coalesced degree terms + g_cur zero + exclusive prefix sum via smem staging
__global__ void k_scan() {
    extern __shared__ int sdyn[];
    int* scnt = sdyn;            // [NN]
    int* wpre = sdyn + NN;       // [32]
    const int t = threadIdx.x;
    const int lane = t & 31, warp = t >> 5;

#pragma unroll
    for (int i = 0; i < 12; i++) {
        int idx = t + (i << 10);
        int c = g_cnt[idx];
        scnt[idx] = c;
        float dv = rsqrtf((float)(c + 1));      // +1 self loop
        g_dinv_sqrt[idx] = dv;
        g_deg_inv[idx]   = dv * dv;
        g_cur[idx] = 0;
    }
    __syncthreads();

    const int base = t * 12;
    int loc[12];
    int s = 0;
#pragma unroll
    for (int i = 0; i < 12; i++) { loc[i] = s; s += scnt[base + i]; }

    int inc = s;
#pragma unroll
    for (int o = 1; o < 32; o <<= 1) {
        int v = __shfl_up_sync(0xFFFFFFFFu, inc, o);
        if (lane >= o) inc += v;
    }
    if (lane == 31) wpre[warp] = inc;
    __syncthreads();
    if (warp == 0) {
        int v = wpre[lane];
        int iv = v;
#pragma unroll
        for (int o = 1; o < 32; o <<= 1) {
            int u = __shfl_up_sync(0xFFFFFFFFu, iv, o);
            if (lane >= o) iv += u;
        }
        wpre[lane] = iv - v;
    }
    __syncthreads();
    const int pre = wpre[warp] + inc - s;

#pragma unroll
    for (int i = 0; i < 12; i++) scnt[base + i] = pre + loc[i];
    __syncthreads();
#pragma unroll
    for (int i = 0; i < 12; i++) {
        int idx = t + (i << 10);
        g_off[idx] = scnt[idx];
    }
    if (t == 1023) g_off[NN] = pre + s;
}

__global__ void k_fill(const int* __restrict__ ei) {
    int e = blockIdx.x * blockDim.x + threadIdx.x;
    if (e < EE) {
        int s = ei[e];
        int d = ei[EE + e];
        if (s >= 0 && s < NN && d >= 0 && d < NN) {
            int pos = g_off[d] + atomicAdd(&g_cur[d], 1);
            g_csr_src[pos]  = s;
            g_csr_norm[pos] = g_dinv_sqrt[s] * g_dinv_sqrt[d];
        }
    }
}

// ---------------- mma helpers ----------------
#define MMA_BF16(d, a, b0, b1)                                                     \
    asm volatile("mma.sync.aligned.m16n8k16.row.col.f32.bf16.bf16.f32 "            \
                 "{%0,%1,%2,%3}, {%4,%5,%6,%7}, {%8,%9}, {%0,%1,%2,%3};"           \
                 : "+f"((d)[0]), "+f"((d)[1]), "+f"((d)[2]), "+f"((d)[3])          \
                 : "r"((a)[0]), "r"((a)[1]), "r"((a)[2]), "r"((a)[3]),             \
                   "r"(b0), "r"(b1))

#define LDSM_X4(r0, r1, r2, r3, addr)                                              \
    asm volatile("ldmatrix.sync.aligned.m8n8.x4.shared.b16 {%0,%1,%2,%3}, [%4];"   \
                 : "=r"(r0), "=r"(r1), "=r"(r2), "=r"(r3) : "r"(addr))

#define LDSM_X4_T(r0, r1, r2, r3, addr)                                                \
    asm volatile("ldmatrix.sync.aligned.m8n8.x4.trans.shared.b16 {%0,%1,%2,%3}, [%4];" \
                 : "=r"(r0), "=r"(r1), "=r"(r2), "=r"(r3) : "r"(addr))

// ---------------- general GEMM on tensor cores with fp32->bf16 hi/lo split ----------------
template<int RELU, int SPLIT, int HAS_BIAS>
__global__ void __launch_bounds__(256) gemm_mma_kernel(
    const float* __restrict__ A, const float* __restrict__ B,
    const float* __restrict__ bias, float* __restrict__ C,
    __nv_bfloat16* __restrict__ Chi, __nv_bfloat16* __restrict__ Clo,
    int K, int F)
{
    extern __shared__ __nv_bfloat16 sm[];
    __nv_bfloat16* Ahi = sm;
    __nv_bfloat16* Alo = Ahi + 128 * SM_STRIDE;
    __nv_bfloat16* Bhi = Alo + 128 * SM_STRIDE;
    __nv_bfloat16* Blo = Bhi + 64 * SM_STRIDE;

    const int tid  = threadIdx.x;
    const int lane = tid & 31;
    const int wid  = tid >> 5;
    const int row0 = blockIdx.y << 7;
    const int col0 = blockIdx.x << 6;

    const int wm = (wid >> 1) << 5;
    const int wn = (wid & 1) << 5;

    float acc[2][4][4];
#pragma unroll
    for (int mt = 0; mt < 2; mt++)
#pragma unroll
        for (int nt = 0; nt < 4; nt++)
#pragma unroll
            for (int r = 0; r < 4; r++) acc[mt][nt][r] = 0.f;

    const int lr  = lane & 7;
    const int grp = lane >> 3;
    const int a_m = lr + ((grp & 1) << 3);
    const int a_k = (grp >> 1) << 3;
    const int bt_k = lr + ((grp & 1) << 3);
    const int bt_n = (grp >> 1) << 3;

    const uint32_t ahiB = (uint32_t)__cvta_generic_to_shared(Ahi);
    const uint32_t aloB = (uint32_t)__cvta_generic_to_shared(Alo);
    const uint32_t bhiB = (uint32_t)__cvta_generic_to_shared(Bhi);
    const uint32_t bloB = (uint32_t)__cvta_generic_to_shared(Blo);

    for (int k0 = 0; k0 < K; k0 += 64) {
        if (k0) __syncthreads();
#pragma unroll
        for (int i = tid; i < 2048; i += 256) {
            int r = i >> 4, c = (i & 15) << 2;
            float4 v = *(const float4*)&A[(size_t)(row0 + r) * K + k0 + c];
            __nv_bfloat162 h01 = __floats2bfloat162_rn(v.x, v.y);
            __nv_bfloat162 h23 = __floats2bfloat162_rn(v.z, v.w);
            __nv_bfloat162 l01 = __floats2bfloat162_rn(v.x - __bfloat162float(h01.x),
                                                       v.y - __bfloat162float(h01.y));
            __nv_bfloat162 l23 = __floats2bfloat162_rn(v.z - __bfloat162float(h23.x),
                                                       v.w - __bfloat162float(h23.y));
            *(__nv_bfloat162*)&Ahi[r * SM_STRIDE + c]     = h01;
            *(__nv_bfloat162*)&Ahi[r * SM_STRIDE + c + 2] = h23;
            *(__nv_bfloat162*)&Alo[r * SM_STRIDE + c]     = l01;
            *(__nv_bfloat162*)&Alo[r * SM_STRIDE + c + 2] = l23;
        }
#pragma unroll
        for (int i = tid; i < 1024; i += 256) {
            int r = i >> 4, c = (i & 15) << 2;
            float4 v = *(const float4*)&B[(size_t)(k0 + r) * F + col0 + c];
            __nv_bfloat162 h01 = __floats2bfloat162_rn(v.x, v.y);
            __nv_bfloat162 h23 = __floats2bfloat162_rn(v.z, v.w);
            __nv_bfloat162 l01 = __floats2bfloat162_rn(v.x - __bfloat162float(h01.x),
                                                       v.y - __bfloat162float(h01.y));
            __nv_bfloat162 l23 = __floats2bfloat162_rn(v.z - __bfloat162float(h23.x),
                                                       v.w - __bfloat162float(h23.y));
            *(__nv_bfloat162*)&Bhi[r * SM_STRIDE + c]     = h01;
            *(__nv_bfloat162*)&Bhi[r * SM_STRIDE + c + 2] = h23;
            *(__nv_bfloat162*)&Blo[r * SM_STRIDE + c]     = l01;
            *(__nv_bfloat162*)&Blo[r * SM_STRIDE + c + 2] = l23;
        }
        __syncthreads();

#pragma unroll
        for (int ks = 0; ks < 4; ks++) {
            const int kk = ks << 4;
            uint32_t ah[2][4], al[2][4];
#pragma unroll
            for (int mt = 0; mt < 2; mt++) {
                uint32_t off = (uint32_t)(((wm + (mt << 4) + a_m) * SM_STRIDE + kk + a_k) << 1);
                LDSM_X4(ah[mt][0], ah[mt][1], ah[mt][2], ah[mt][3], ahiB + off);
                LDSM_X4(al[mt][0], al[mt][1], al[mt][2], al[mt][3], aloB + off);
            }
#pragma unroll
            for (int np = 0; np < 2; np++) {
                uint32_t off = (uint32_t)(((kk + bt_k) * SM_STRIDE + wn + (np << 4) + bt_n) << 1);
                uint32_t bh[4], bl[4];
                LDSM_X4_T(bh[0], bh[1], bh[2], bh[3], bhiB + off);
                LDSM_X4_T(bl[0], bl[1], bl[2], bl[3], bloB + off);
#pragma unroll
                for (int mt = 0; mt < 2; mt++) {
                    float* d0 = acc[mt][2 * np];
                    float* d1 = acc[mt][2 * np + 1];
                    MMA_BF16(d0, ah[mt], bh[0], bh[1]);
                    MMA_BF16(d1, ah[mt], bh[2], bh[3]);
                    MMA_BF16(d0, ah[mt], bl[0], bl[1]);
                    MMA_BF16(d1, ah[mt], bl[2], bl[3]);
                    MMA_BF16(d0, al[mt], bh[0], bh[1]);
                    MMA_BF16(d1, al[mt], bh[2], bh[3]);
                }
            }
        }
    }

    const int crow = lane >> 2;
    const int ccol = (lane & 3) << 1;
#pragma unroll
    for (int mt = 0; mt < 2; mt++) {
#pragma unroll
        for (int nt = 0; nt < 4; nt++) {
            int row = row0 + wm + (mt << 4) + crow;
            int col = col0 + wn + (nt << 3) + ccol;
            float v0 = acc[mt][nt][0], v1 = acc[mt][nt][1];
            float v2 = acc[mt][nt][2], v3 = acc[mt][nt][3];
            if (HAS_BIAS) {
                float2 bb = *(const float2*)&bias[col];
                v0 += bb.x; v1 += bb.y; v2 += bb.x; v3 += bb.y;
            }
            if (RELU) {
                v0 = fmaxf(v0, 0.f); v1 = fmaxf(v1, 0.f);
                v2 = fmaxf(v2, 0.f); v3 = fmaxf(v3, 0.f);
            }
            if (SPLIT) {
                __nv_bfloat162 h0 = __floats2bfloat162_rn(v0, v1);
                __nv_bfloat162 h1v = __floats2bfloat162_rn(v2, v3);
                __nv_bfloat162 l0 = __floats2bfloat162_rn(v0 - __bfloat162float(h0.x),
                                                          v1 - __bfloat162float(h0.y));
                __nv_bfloat162 l1 = __floats2bfloat162_rn(v2 - __bfloat162float(h1v.x),
                                                          v3 - __bfloat162float(h1v.y));
                *(__nv_bfloat162*)&Chi[(size_t)row * F + col]       = h0;
                *(__nv_bfloat162*)&Chi[(size_t)(row + 8) * F + col] = h1v;
                *(__nv_bfloat162*)&Clo[(size_t)row * F + col]       = l0;
                *(__nv_bfloat162*)&Clo[(size_t)(row + 8) * F + col] = l1;
            } else {
                *(float2*)&C[(size_t)row * F + col]       = make_float2(v0, v1);
                *(float2*)&C[(size_t)(row + 8) * F + col] = make_float2(v2, v3);
            }
        }
    }
}

// ---------------- symmetric syrk (R10: triangular 2D grid, direct stores + smem mirror) ----------------
__global__ void __launch_bounds__(256, 2) syrk_mma_kernel(
    const __nv_bfloat16* __restrict__ Shi,
    const __nv_bfloat16* __restrict__ Slo,
    float* __restrict__ C)
{
    if (blockIdx.y > blockIdx.x) return;

    extern __shared__ __nv_bfloat16 sm[];
    __nv_bfloat16* Ahi = sm;
    __nv_bfloat16* Alo = sm + 128 * SM_STRIDE;
    __nv_bfloat16* Bhi = sm + 2 * 128 * SM_STRIDE;
    __nv_bfloat16* Blo = sm + 3 * 128 * SM_STRIDE;

    const int tid  = threadIdx.x;
    const int lane = tid & 31;
    const int wid  = tid >> 5;
    const int row0 = blockIdx.y << 7;
    const int col0 = blockIdx.x << 7;
    const bool diag = (blockIdx.x == blockIdx.y);

    for (int i = tid; i < 1024; i += 256) {
        int r = i >> 3, c = (i & 7) << 3;
        *(uint4*)(Ahi + r * SM_STRIDE + c) = *(const uint4*)(Shi + (size_t)(row0 + r) * 64 + c);
        *(uint4*)(Alo + r * SM_STRIDE + c) = *(const uint4*)(Slo + (size_t)(row0 + r) * 64 + c);
        *(uint4*)(Bhi + r * SM_STRIDE + c) = *(const uint4*)(Shi + (size_t)(col0 + r) * 64 + c);
        *(uint4*)(Blo + r * SM_STRIDE + c) = *(const uint4*)(Slo + (size_t)(col0 + r) * 64 + c);
    }
    __syncthreads();

    const int wm = (wid >> 1) << 5;
    const int wn = (wid & 1) << 6;

    float acc[2][8][4];
#pragma unroll
    for (int mt = 0; mt < 2; mt++)
#pragma unroll
        for (int nt = 0; nt < 8; nt++)
#pragma unroll
            for (int r = 0; r < 4; r++) acc[mt][nt][r] = 0.f;

    const int lr  = lane & 7;
    const int grp = lane >> 3;
    const int a_m = lr + ((grp & 1) << 3);
    const int a_k = (grp >> 1) << 3;
    const int b_n = lr + ((grp >> 1) << 3);
    const int b_k = (grp & 1) << 3;

    const uint32_t ahiB = (uint32_t)__cvta_generic_to_shared(Ahi);
    const uint32_t aloB = (uint32_t)__cvta_generic_to_shared(Alo);
    const uint32_t bhiB = (uint32_t)__cvta_generic_to_shared(Bhi);
    const uint32_t bloB = (uint32_t)__cvta_generic_to_shared(Blo);

#pragma unroll
    for (int ks = 0; ks < 4; ks++) {
        const int k0 = ks << 4;
        uint32_t ah[2][4], al[2][4];
#pragma unroll
        for (int mt = 0; mt < 2; mt++) {
            uint32_t off = (uint32_t)(((wm + (mt << 4) + a_m) * SM_STRIDE + k0 + a_k) << 1);
            LDSM_X4(ah[mt][0], ah[mt][1], ah[mt][2], ah[mt][3], ahiB + off);
            LDSM_X4(al[mt][0], al[mt][1], al[mt][2], al[mt][3], aloB + off);
        }
#pragma unroll
        for (int np = 0; np < 4; np++) {
            uint32_t off = (uint32_t)(((wn + (np << 4) + b_n) * SM_STRIDE + k0 + b_k) << 1);
            uint32_t bh[4], bl[4];
            LDSM_X4(bh[0], bh[1], bh[2], bh[3], bhiB + off);
            LDSM_X4(bl[0], bl[1], bl[2], bl[3], bloB + off);
#pragma unroll
            for (int mt = 0; mt < 2; mt++) {
                float* d0 = acc[mt][2 * np];
                float* d1 = acc[mt][2 * np + 1];
                MMA_BF16(d0, ah[mt], bh[0], bh[1]);
                MMA_BF16(d1, ah[mt], bh[2], bh[3]);
                MMA_BF16(d0, ah[mt], bl[0], bl[1]);
                MMA_BF16(d1, ah[mt], bl[2], bl[3]);
                MMA_BF16(d0, al[mt], bh[0], bh[1]);
                MMA_BF16(d1, al[mt], bh[2], bh[3]);
            }
        }
    }

    const int crow = lane >> 2;
    const int ccol = (lane & 3) << 1;

#pragma unroll
    for (int mt = 0; mt < 2; mt++) {
#pragma unroll
        for (int nt = 0; nt < 8; nt++) {
            int row = row0 + wm + (mt << 4) + crow;
            int col = col0 + wn + (nt << 3) + ccol;
            *(float2*)&C[(size_t)row * NN + col]       = make_float2(acc[mt][nt][0], acc[mt][nt][1]);
            *(float2*)&C[(size_t)(row + 8) * NN + col] = make_float2(acc[mt][nt][2], acc[mt][nt][3]);
        }
    }

    if (!diag) {
        __syncthreads();
        float* smT = reinterpret_cast<float*>(sm);
#pragma unroll
        for (int mt = 0; mt < 2; mt++) {
#pragma unroll
            for (int nt = 0; nt < 8; nt++) {
                int rl = wm + (mt << 4) + crow;
                int cl = wn + (nt << 3) + ccol;
                smT[(cl)     * T_STRIDE + rl]     = acc[mt][nt][0];
                smT[(cl + 1) * T_STRIDE + rl]     = acc[mt][nt][1];
                smT[(cl)     * T_STRIDE + rl + 8] = acc[mt][nt][2];
                smT[(cl + 1) * T_STRIDE + rl + 8] = acc[mt][nt][3];
            }
        }
        __syncthreads();
#pragma unroll
        for (int i = tid; i < 4096; i += 256) {
            int r  = i >> 5;
            int c4 = (i & 31) << 2;
            float4 v = *(float4*)&smT[r * T_STRIDE + c4];
            *(float4*)&C[(size_t)(col0 + r) * NN + row0 + c4] = v;
        }
    }
}

// ---------------- GCN aggregation (standalone) ----------------
template<int F, int RELU, int HAS_BIAS>
__global__ void __launch_bounds__(256) aggregate_kernel(
    const float* __restrict__ h, const float* __restrict__ bias,
    float* __restrict__ out)
{
    constexpr int VPT = F / 32;
    const int gw   = (blockIdx.x * 256 + threadIdx.x) >> 5;
    const int lane = threadIdx.x & 31;
    if (gw >= NN) return;

    float acc[VPT];
    const float di = g_deg_inv[gw];
    const float* hn = h + (size_t)gw * F;
#pragma unroll
    for (int i = 0; i < VPT; i++) {
        acc[i] = hn[(i << 5) + lane] * di;
        if (HAS_BIAS) acc[i] += bias[(i << 5) + lane];
    }

    int e = g_off[gw];
    const int e1 = g_off[gw + 1];
    for (; e + 1 < e1; e += 2) {
        int   s0 = g_csr_src[e],     s1 = g_csr_src[e + 1];
        float w0 = g_csr_norm[e],    w1 = g_csr_norm[e + 1];
        const float* p0 = h + (size_t)s0 * F;
        const float* p1 = h + (size_t)s1 * F;
#pragma unroll
        for (int i = 0; i < VPT; i++) acc[i] += p0[(i << 5) + lane] * w0;
#pragma unroll
        for (int i = 0; i < VPT; i++) acc[i] += p1[(i << 5) + lane] * w1;
    }
    if (e < e1) {
        int s = g_csr_src[e];
        float w = g_csr_norm[e];
        const float* p = h + (size_t)s * F;
#pragma unroll
        for (int i = 0; i < VPT; i++) acc[i] += p[(i << 5) + lane] * w;
    }
#pragma unroll
    for (int i = 0; i < VPT; i++) {
        float v = acc[i];
        if (RELU) v = fmaxf(v, 0.f);
        out[(size_t)gw * F + (i << 5) + lane] = v;
    }
}

// ---------------- fused: agg(F=128)+bias+relu, then row @ W[128,64] ----------------
// out[gw] = relu(bias + h[gw]*di + sum h[src]*norm) @ W     (h1 never materialized)
__global__ void __launch_bounds__(256) agg_gemm_e2_kernel(
    const float* __restrict__ h, const float* __restrict__ bias,
    const float* __restrict__ W, float* __restrict__ out)
{
    extern __shared__ float sW[];                  // [128*64]
    const int tid  = threadIdx.x;
    const int lane = tid & 31;
    for (int i = tid; i < 128 * 64; i += 256) sW[i] = W[i];
    __syncthreads();

    const int warps_total = gridDim.x * 8;
    for (int gw = (blockIdx.x * 256 + tid) >> 5; gw < NN; gw += warps_total) {
        float acc[4];
        const float di = g_deg_inv[gw];
        const float* hn = h + (size_t)gw * 128;
#pragma unroll
        for (int i = 0; i < 4; i++)
            acc[i] = hn[(i << 5) + lane] * di + bias[(i << 5) + lane];

        int e = g_off[gw];
        const int e1 = g_off[gw + 1];
        for (; e + 1 < e1; e += 2) {
            int   s0 = g_csr_src[e],  s1 = g_csr_src[e + 1];
            float w0 = g_csr_norm[e], w1 = g_csr_norm[e + 1];
            const float* p0 = h + (size_t)s0 * 128;
            const float* p1 = h + (size_t)s1 * 128;
#pragma unroll
            for (int i = 0; i < 4; i++) acc[i] += p0[(i << 5) + lane] * w0;
#pragma unroll
            for (int i = 0; i < 4; i++) acc[i] += p1[(i << 5) + lane] * w1;
        }
        if (e < e1) {
            int s = g_csr_src[e];
            float w = g_csr_norm[e];
            const float* p = h + (size_t)s * 128;
#pragma unroll
            for (int i = 0; i < 4; i++) acc[i] += p[(i << 5) + lane] * w;
        }
#pragma unroll
        for (int i = 0; i < 4; i++) acc[i] = fmaxf(acc[i], 0.f);

        // row @ W via shfl-broadcast; lane owns cols 2*lane, 2*lane+1
        float o0 = 0.f, o1 = 0.f;
#pragma unroll
        for (int seg = 0; seg < 4; seg++) {
            float src = acc[seg];
#pragma unroll
            for (int kk = 0; kk < 32; kk++) {
                float hk = __shfl_sync(0xFFFFFFFFu, src, kk);
                float2 w = *(const float2*)&sW[(((seg << 5) + kk) << 6) + (lane << 1)];
                o0 += hk * w.x; o1 += hk * w.y;
            }
        }
        *(float2*)&out[(size_t)gw * 64 + (lane << 1)] = make_float2(o0, o1);
    }
}

// ---------------- fused: zagg = agg(z), then both decoder heads ----------------
// a = relu(zagg @ W_a1 + b_a1) [NN,128];  s = relu(zagg @ W_s + b_s) -> hi/lo bf16
__global__ void __launch_bounds__(256) agg_decoders_kernel(
    const float* __restrict__ z,
    const float* __restrict__ Wa, const float* __restrict__ ba,
    const float* __restrict__ Ws, const float* __restrict__ bs,
    float* __restrict__ a_out,
    __nv_bfloat16* __restrict__ s_hi, __nv_bfloat16* __restrict__ s_lo)
{
    extern __shared__ float sWgt[];                // Wa[64*128] + Ws[64*64]
    float* sWa = sWgt;
    float* sWs = sWgt + 64 * 128;
    const int tid  = threadIdx.x;
    const int lane = tid & 31;
    for (int i = tid; i < 64 * 128; i += 256) sWa[i] = Wa[i];
    for (int i = tid; i < 64 * 64;  i += 256) sWs[i] = Ws[i];
    __syncthreads();

    const int warps_total = gridDim.x * 8;
    for (int gw = (blockIdx.x * 256 + tid) >> 5; gw < NN; gw += warps_total) {
        float acc[2];
        const float di = g_deg_inv[gw];
        const float* zn = z + (size_t)gw * 64;
        acc[0] = zn[lane] * di;
        acc[1] = zn[32 + lane] * di;

        int e = g_off[gw];
        const int e1 = g_off[gw + 1];
        for (; e + 1 < e1; e += 2) {
            int   s0 = g_csr_src[e],  s1 = g_csr_src[e + 1];
            float w0 = g_csr_norm[e], w1 = g_csr_norm[e + 1];
            const float* p0 = z + (size_t)s0 * 64;
            const float* p1 = z + (size_t)s1 * 64;
            acc[0] += p0[lane] * w0;      acc[1] += p0[32 + lane] * w0;
            acc[0] += p1[lane] * w1;      acc[1] += p1[32 + lane] * w1;
        }
        if (e < e1) {
            int s = g_csr_src[e];
            float w = g_csr_norm[e];
            const float* p = z + (size_t)s * 64;
            acc[0] += p[lane] * w;        acc[1] += p[32 + lane] * w;
        }

        // both heads via shfl-broadcast
        float aa0 = 0.f, aa1 = 0.f, aa2 = 0.f, aa3 = 0.f;   // cols 4l..4l+3 of a
        float ss0 = 0.f, ss1 = 0.f;                         // cols 2l..2l+1 of s
#pragma unroll
        for (int seg = 0; seg < 2; seg++) {
            float src = acc[seg];
#pragma unroll
            for (int kk = 0; kk < 32; kk++) {
                float zk = __shfl_sync(0xFFFFFFFFu, src, kk);
                int k = (seg << 5) + kk;
                float4 wa = *(const float4*)&sWa[(k << 7) + (lane << 2)];
                float2 ws = *(const float2*)&sWs[(k << 6) + (lane << 1)];
                aa0 += zk * wa.x; aa1 += zk * wa.y; aa2 += zk * wa.z; aa3 += zk * wa.w;
                ss0 += zk * ws.x; ss1 += zk * ws.y;
            }
        }
        float4 bav = *(const float4*)&ba[lane << 2];
        float2 bsv = *(const float2*)&bs[lane << 1];
        aa0 = fmaxf(aa0 + bav.x, 0.f); aa1 = fmaxf(aa1 + bav.y, 0.f);
        aa2 = fmaxf(aa2 + bav.z, 0.f); aa3 = fmaxf(aa3 + bav.w, 0.f);
        ss0 = fmaxf(ss0 + bsv.x, 0.f); ss1 = fmaxf(ss1 + bsv.y, 0.f);

        *(float4*)&a_out[(size_t)gw * 128 + (lane << 2)] = make_float4(aa0, aa1, aa2, aa3);

        __nv_bfloat162 hi = __floats2bfloat162_rn(ss0, ss1);
        __nv_bfloat162 lo = __floats2bfloat162_rn(ss0 - __bfloat162float(hi.x),
                                                  ss1 - __bfloat162float(hi.y));
        *(__nv_bfloat162*)&s_hi[(size_t)gw * 64 + (lane << 1)] = hi;
        *(__nv_bfloat162*)&s_lo[(size_t)gw * 64 + (lane << 1)] = lo;
    }
}

// ---------------- launch ----------------
extern "C" void kernel_launch(void* const* d_in, const int* in_sizes, int n_in,
                              void* d_out, int out_size)
{
    const float* x    = (const float*)d_in[0];
    const int*   ei   = (const int*)d_in[1];     // int32 on device
    const float* W_e1 = (const float*)d_in[2];
    const float* b_e1 = (const float*)d_in[3];
    const float* W_e2 = (const float*)d_in[4];
    const float* b_e2 = (const float*)d_in[5];
    const float* W_a1 = (const float*)d_in[6];
    const float* b_a1 = (const float*)d_in[7];
    const float* W_a2 = (const float*)d_in[8];
    const float* b_a2 = (const float*)d_in[9];
    const float* W_s  = (const float*)d_in[10];
    const float* b_s  = (const float*)d_in[11];

    float* out   = (float*)d_out;
    float* x_hat = out;                                 // [NN, 256]
    float* a_hat = out + (size_t)NN * 256;              // [NN, NN]
    float* zout  = a_hat + (size_t)NN * NN;             // [NN, 64]

    float *p_tmp, *p_h1, *p_a;
    __nv_bfloat16 *p_shi, *p_slo;
    cudaGetSymbolAddress((void**)&p_tmp, g_tmp);
    cudaGetSymbolAddress((void**)&p_h1,  g_h1);
    cudaGetSymbolAddress((void**)&p_a,   g_a);
    cudaGetSymbolAddress((void**)&p_shi, g_s_hi);
    cudaGetSymbolAddress((void**)&p_slo, g_s_lo);

    const int gemm_smem = (128 + 128 + 64 + 64) * SM_STRIDE * 2;   // 55296 B
    const int syrk_smem = 4 * 128 * SM_STRIDE * 2;                 // 73728 B
    const int scan_smem = (NN + 32) * 4;                           // 49280 B
    const int aggA_smem = 128 * 64 * 4;                            // 32768 B
    const int aggB_smem = (64 * 128 + 64 * 64) * 4;                // 49152 B

    static cudaStream_t s_side = nullptr;
    static cudaEvent_t  ev_fork, ev_l1, ev_dec, ev_side_done;
    if (!s_side) {
        cudaStreamCreateWithFlags(&s_side, cudaStreamNonBlocking);
        cudaEventCreateWithFlags(&ev_fork,      cudaEventDisableTiming);
        cudaEventCreateWithFlags(&ev_l1,        cudaEventDisableTiming);
        cudaEventCreateWithFlags(&ev_dec,       cudaEventDisableTiming);
        cudaEventCreateWithFlags(&ev_side_done, cudaEventDisableTiming);
        cudaFuncSetAttribute(gemm_mma_kernel<0,0,0>, cudaFuncAttributeMaxDynamicSharedMemorySize, gemm_smem);
        cudaFuncSetAttribute(gemm_mma_kernel<0,0,1>, cudaFuncAttributeMaxDynamicSharedMemorySize, gemm_smem);
        cudaFuncSetAttribute(syrk_mma_kernel, cudaFuncAttributeMaxDynamicSharedMemorySize, syrk_smem);
        cudaFuncSetAttribute(k_scan, cudaFuncAttributeMaxDynamicSharedMemorySize, scan_smem);
        cudaFuncSetAttribute(agg_gemm_e2_kernel, cudaFuncAttributeMaxDynamicSharedMemorySize, aggA_smem);
        cudaFuncSetAttribute(agg_decoders_kernel, cudaFuncAttributeMaxDynamicSharedMemorySize, aggB_smem);
    }

    // ---- fork: side stream runs the encoder-L1 GEMM while main builds CSR ----
    cudaEventRecord(ev_fork, 0);
    cudaStreamWaitEvent(s_side, ev_fork, 0);

    gemm_mma_kernel<0,0,0><<<dim3(2, 96), 256, gemm_smem, s_side>>>(
        x, W_e1, nullptr, p_tmp, nullptr, nullptr, 256, 128);
    cudaEventRecord(ev_l1, s_side);

    // main: CSR build (int atomics only)
    k_init <<<48,   256>>>();
    k_count<<<1536, 256>>>(ei);
    k_scan <<<1,    1024, scan_smem>>>();
    k_fill <<<1536, 256>>>(ei);

    cudaStreamWaitEvent(0, ev_l1, 0);

    // fused: h1 = relu(agg(L1)+b_e1); tmp2 = h1 @ W_e2   (h1 not materialized)
    agg_gemm_e2_kernel<<<444, 256, aggA_smem>>>(p_tmp, b_e1, W_e2, p_h1);

    // z = relu(agg(tmp2) + b_e2) -> output
    aggregate_kernel<64, 1, 1><<<1536, 256>>>(p_h1, b_e2, zout);

    // fused: zagg = agg(z); a = relu(zagg@W_a1+b); s = relu(zagg@W_s+b) -> hi/lo
    agg_decoders_kernel<<<444, 256, aggB_smem>>>(zout, W_a1, b_a1, W_s, b_s,
                                                 p_a, p_shi, p_slo);
    cudaEventRecord(ev_dec, 0);

    // ---- main stream: syrk (long pole) starts immediately ----
    syrk_mma_kernel<<<dim3(96, 96), 256, syrk_smem>>>(p_shi, p_slo, a_hat);

    // ---- side stream: attribute branch (hidden under syrk) ----
    cudaStreamWaitEvent(s_side, ev_dec, 0);
    aggregate_kernel<128, 0, 0><<<1536, 256, 0, s_side>>>(p_a, nullptr, p_h1);
    gemm_mma_kernel<0,0,1><<<dim3(4, 96), 256, gemm_smem, s_side>>>(
        p_h1, W_a2, b_a2, x_hat, nullptr, nullptr, 128, 256);
    cudaEventRecord(ev_side_done, s_side);

    cudaStreamWaitEvent(0, ev_side_done, 0);
}

// round 13
// speedup vs baseline: 1.2152x; 1.2152x over previous
#include <cuda_runtime.h>
#include <cuda_bf16.h>
#include <cstdint>

#define NN 12288
#define EE 393216
#define SM_STRIDE 72   // bf16 elems per row (144B; 144 mod 128 = 16 -> conflict-free)
#define T_STRIDE 132   // fp32 transpose staging stride (128+4)

// ---------------- scratch (static device globals; no allocation) ----------------
static __device__ float g_tmp[NN * 256];
static __device__ float g_h1 [NN * 128];
static __device__ float g_a  [NN * 128];
static __device__ __nv_bfloat16 g_s_hi[NN * 64];
static __device__ __nv_bfloat16 g_s_lo[NN * 64];

static __device__ int   g_cnt[NN];
static __device__ int   g_cur[NN];
static __device__ int   g_off[NN + 1];
static __device__ int   g_csr_src[EE];
static __device__ float g_csr_norm[EE];
static __device__ float g_dinv_sqrt[NN];
static __device__ float g_deg_inv[NN];

// ---------------- CSR construction ----------------
__global__ void k_init() {
    int i = blockIdx.x * blockDim.x + threadIdx.x;
    if (i < NN) g_cnt[i] = 0;
}

// edge_index is int32 on device (JAX x64 disabled downcasts jnp.int64).
// 2 edges per thread via int2 (coalesced, half the instructions/blocks).
__global__ void k_count(const int* __restrict__ ei) {
    int e2 = blockIdx.x * blockDim.x + threadIdx.x;
    if (e2 < EE / 2) {
        int2 d = *(const int2*)&ei[EE + 2 * e2];
        if (d.x >= 0 && d.x < NN) atomicAdd(&g_cnt[d.x], 1);
        if (d.y >= 0 && d.y < NN) atomicAdd(&g_cnt[d.y], 1);
    }
}

// fused: coalesced degree terms + g_cur zero + exclusive prefix sum via smem staging
__global__ void k_scan() {
    extern __shared__ int sdyn[];
    int* scnt = sdyn;            // [NN]
    int* wpre = sdyn + NN;       // [32]
    const int t = threadIdx.x;
    const int lane = t & 31, warp = t >> 5;

#pragma unroll
    for (int i = 0; i < 12; i++) {
        int idx = t + (i << 10);
        int c = g_cnt[idx];
        scnt[idx] = c;
        float dv = rsqrtf((float)(c + 1));      // +1 self loop
        g_dinv_sqrt[idx] = dv;
        g_deg_inv[idx]   = dv * dv;
        g_cur[idx] = 0;
    }
    __syncthreads();

    const int base = t * 12;
    int loc[12];
    int s = 0;
#pragma unroll
    for (int i = 0; i < 12; i++) { loc[i] = s; s += scnt[base + i]; }

    int inc = s;
#pragma unroll
    for (int o = 1; o < 32; o <<= 1) {
        int v = __shfl_up_sync(0xFFFFFFFFu, inc, o);
        if (lane >= o) inc += v;
    }
    if (lane == 31) wpre[warp] = inc;
    __syncthreads();
    if (warp == 0) {
        int v = wpre[lane];
        int iv = v;
#pragma unroll
        for (int o = 1; o < 32; o <<= 1) {
            int u = __shfl_up_sync(0xFFFFFFFFu, iv, o);
            if (lane >= o) iv += u;
        }
        wpre[lane] = iv - v;
    }
    __syncthreads();
    const int pre = wpre[warp] + inc - s;

#pragma unroll
    for (int i = 0; i < 12; i++) scnt[base + i] = pre + loc[i];
    __syncthreads();
#pragma unroll
    for (int i = 0; i < 12; i++) {
        int idx = t + (i << 10);
        g_off[idx] = scnt[idx];
    }
    if (t == 1023) g_off[NN] = pre + s;
}

__global__ void k_fill(const int* __restrict__ ei) {
    int e2 = blockIdx.x * blockDim.x + threadIdx.x;
    if (e2 < EE / 2) {
        int2 sv = *(const int2*)&ei[2 * e2];
        int2 dv = *(const int2*)&ei[EE + 2 * e2];
        if (sv.x >= 0 && sv.x < NN && dv.x >= 0 && dv.x < NN) {
            int pos = g_off[dv.x] + atomicAdd(&g_cur[dv.x], 1);
            g_csr_src[pos]  = sv.x;
            g_csr_norm[pos] = g_dinv_sqrt[sv.x] * g_dinv_sqrt[dv.x];
        }
        if (sv.y >= 0 && sv.y < NN && dv.y >= 0 && dv.y < NN) {
            int pos = g_off[dv.y] + atomicAdd(&g_cur[dv.y], 1);
            g_csr_src[pos]  = sv.y;
            g_csr_norm[pos] = g_dinv_sqrt[sv.y] * g_dinv_sqrt[dv.y];
        }
    }
}

// ---------------- mma helpers ----------------
#define MMA_BF16(d, a, b0, b1)                                                     \
    asm volatile("mma.sync.aligned.m16n8k16.row.col.f32.bf16.bf16.f32 "            \
                 "{%0,%1,%2,%3}, {%4,%5,%6,%7}, {%8,%9}, {%0,%1,%2,%3};"           \
                 : "+f"((d)[0]), "+f"((d)[1]), "+f"((d)[2]), "+f"((d)[3])          \
                 : "r"((a)[0]), "r"((a)[1]), "r"((a)[2]), "r"((a)[3]),             \
                   "r"(b0), "r"(b1))

#define LDSM_X4(r0, r1, r2, r3, addr)                                              \
    asm volatile("ldmatrix.sync.aligned.m8n8.x4.shared.b16 {%0,%1,%2,%3}, [%4];"   \
                 : "=r"(r0), "=r"(r1), "=r"(r2), "=r"(r3) : "r"(addr))

#define LDSM_X4_T(r0, r1, r2, r3, addr)                                                \
    asm volatile("ldmatrix.sync.aligned.m8n8.x4.trans.shared.b16 {%0,%1,%2,%3}, [%4];" \
                 : "=r"(r0), "=r"(r1), "=r"(r2), "=r"(r3) : "r"(addr))

// ---------------- general GEMM on tensor cores with fp32->bf16 hi/lo split ----------------
template<int RELU, int SPLIT, int HAS_BIAS>
__global__ void __launch_bounds__(256) gemm_mma_kernel(
    const float* __restrict__ A, const float* __restrict__ B,
    const float* __restrict__ bias, float* __restrict__ C,
    __nv_bfloat16* __restrict__ Chi, __nv_bfloat16* __restrict__ Clo,
    int K, int F)
{
    extern __shared__ __nv_bfloat16 sm[];
    __nv_bfloat16* Ahi = sm;
    __nv_bfloat16* Alo = Ahi + 128 * SM_STRIDE;
    __nv_bfloat16* Bhi = Alo + 128 * SM_STRIDE;
    __nv_bfloat16* Blo = Bhi + 64 * SM_STRIDE;

    const int tid  = threadIdx.x;
    const int lane = tid & 31;
    const int wid  = tid >> 5;
    const int row0 = blockIdx.y << 7;
    const int col0 = blockIdx.x << 6;

    const int wm = (wid >> 1) << 5;
    const int wn = (wid & 1) << 5;

    float acc[2][4][4];
#pragma unroll
    for (int mt = 0; mt < 2; mt++)
#pragma unroll
        for (int nt = 0; nt < 4; nt++)
#pragma unroll
            for (int r = 0; r < 4; r++) acc[mt][nt][r] = 0.f;

    const int lr  = lane & 7;
    const int grp = lane >> 3;
    const int a_m = lr + ((grp & 1) << 3);
    const int a_k = (grp >> 1) << 3;
    const int bt_k = lr + ((grp & 1) << 3);
    const int bt_n = (grp >> 1) << 3;

    const uint32_t ahiB = (uint32_t)__cvta_generic_to_shared(Ahi);
    const uint32_t aloB = (uint32_t)__cvta_generic_to_shared(Alo);
    const uint32_t bhiB = (uint32_t)__cvta_generic_to_shared(Bhi);
    const uint32_t bloB = (uint32_t)__cvta_generic_to_shared(Blo);

    for (int k0 = 0; k0 < K; k0 += 64) {
        if (k0) __syncthreads();
#pragma unroll
        for (int i = tid; i < 2048; i += 256) {
            int r = i >> 4, c = (i & 15) << 2;
            float4 v = *(const float4*)&A[(size_t)(row0 + r) * K + k0 + c];
            __nv_bfloat162 h01 = __floats2bfloat162_rn(v.x, v.y);
            __nv_bfloat162 h23 = __floats2bfloat162_rn(v.z, v.w);
            __nv_bfloat162 l01 = __floats2bfloat162_rn(v.x - __bfloat162float(h01.x),
                                                       v.y - __bfloat162float(h01.y));
            __nv_bfloat162 l23 = __floats2bfloat162_rn(v.z - __bfloat162float(h23.x),
                                                       v.w - __bfloat162float(h23.y));
            *(__nv_bfloat162*)&Ahi[r * SM_STRIDE + c]     = h01;
            *(__nv_bfloat162*)&Ahi[r * SM_STRIDE + c + 2] = h23;
            *(__nv_bfloat162*)&Alo[r * SM_STRIDE + c]     = l01;
            *(__nv_bfloat162*)&Alo[r * SM_STRIDE + c + 2] = l23;
        }
#pragma unroll
        for (int i = tid; i < 1024; i += 256) {
            int r = i >> 4, c = (i & 15) << 2;
            float4 v = *(const float4*)&B[(size_t)(k0 + r) * F + col0 + c];
            __nv_bfloat162 h01 = __floats2bfloat162_rn(v.x, v.y);
            __nv_bfloat162 h23 = __floats2bfloat162_rn(v.z, v.w);
            __nv_bfloat162 l01 = __floats2bfloat162_rn(v.x - __bfloat162float(h01.x),
                                                       v.y - __bfloat162float(h01.y));
            __nv_bfloat162 l23 = __floats2bfloat162_rn(v.z - __bfloat162float(h23.x),
                                                       v.w - __bfloat162float(h23.y));
            *(__nv_bfloat162*)&Bhi[r * SM_STRIDE + c]     = h01;
            *(__nv_bfloat162*)&Bhi[r * SM_STRIDE + c + 2] = h23;
            *(__nv_bfloat162*)&Blo[r * SM_STRIDE + c]     = l01;
            *(__nv_bfloat162*)&Blo[r * SM_STRIDE + c + 2] = l23;
        }
        __syncthreads();

#pragma unroll
        for (int ks = 0; ks < 4; ks++) {
            const int kk = ks << 4;
            uint32_t ah[2][4], al[2][4];
#pragma unroll
            for (int mt = 0; mt < 2; mt++) {
                uint32_t off = (uint32_t)(((wm + (mt << 4) + a_m) * SM_STRIDE + kk + a_k) << 1);
                LDSM_X4(ah[mt][0], ah[mt][1], ah[mt][2], ah[mt][3], ahiB + off);
                LDSM_X4(al[mt][0], al[mt][1], al[mt][2], al[mt][3], aloB + off);
            }
#pragma unroll
            for (int np = 0; np < 2; np++) {
                uint32_t off = (uint32_t)(((kk + bt_k) * SM_STRIDE + wn + (np << 4) + bt_n) << 1);
                uint32_t bh[4], bl[4];
                LDSM_X4_T(bh[0], bh[1], bh[2], bh[3], bhiB + off);
                LDSM_X4_T(bl[0], bl[1], bl[2], bl[3], bloB + off);
#pragma unroll
                for (int mt = 0; mt < 2; mt++) {
                    float* d0 = acc[mt][2 * np];
                    float* d1 = acc[mt][2 * np + 1];
                    MMA_BF16(d0, ah[mt], bh[0], bh[1]);
                    MMA_BF16(d1, ah[mt], bh[2], bh[3]);
                    MMA_BF16(d0, ah[mt], bl[0], bl[1]);
                    MMA_BF16(d1, ah[mt], bl[2], bl[3]);
                    MMA_BF16(d0, al[mt], bh[0], bh[1]);
                    MMA_BF16(d1, al[mt], bh[2], bh[3]);
                }
            }
        }
    }

    const int crow = lane >> 2;
    const int ccol = (lane & 3) << 1;
#pragma unroll
    for (int mt = 0; mt < 2; mt++) {
#pragma unroll
        for (int nt = 0; nt < 4; nt++) {
            int row = row0 + wm + (mt << 4) + crow;
            int col = col0 + wn + (nt << 3) + ccol;
            float v0 = acc[mt][nt][0], v1 = acc[mt][nt][1];
            float v2 = acc[mt][nt][2], v3 = acc[mt][nt][3];
            if (HAS_BIAS) {
                float2 bb = *(const float2*)&bias[col];
                v0 += bb.x; v1 += bb.y; v2 += bb.x; v3 += bb.y;
            }
            if (RELU) {
                v0 = fmaxf(v0, 0.f); v1 = fmaxf(v1, 0.f);
                v2 = fmaxf(v2, 0.f); v3 = fmaxf(v3, 0.f);
            }
            if (SPLIT) {
                __nv_bfloat162 h0 = __floats2bfloat162_rn(v0, v1);
                __nv_bfloat162 h1v = __floats2bfloat162_rn(v2, v3);
                __nv_bfloat162 l0 = __floats2bfloat162_rn(v0 - __bfloat162float(h0.x),
                                                          v1 - __bfloat162float(h0.y));
                __nv_bfloat162 l1 = __floats2bfloat162_rn(v2 - __bfloat162float(h1v.x),
                                                          v3 - __bfloat162float(h1v.y));
                *(__nv_bfloat162*)&Chi[(size_t)row * F + col]       = h0;
                *(__nv_bfloat162*)&Chi[(size_t)(row + 8) * F + col] = h1v;
                *(__nv_bfloat162*)&Clo[(size_t)row * F + col]       = l0;
                *(__nv_bfloat162*)&Clo[(size_t)(row + 8) * F + col] = l1;
            } else {
                *(float2*)&C[(size_t)row * F + col]       = make_float2(v0, v1);
                *(float2*)&C[(size_t)(row + 8) * F + col] = make_float2(v2, v3);
            }
        }
    }
}

// ---------------- symmetric syrk via bf16 tensor cores (3-product hi/lo, triangular) ----------------
__global__ void __launch_bounds__(256, 2) syrk_mma_kernel(
    const __nv_bfloat16* __restrict__ Shi,
    const __nv_bfloat16* __restrict__ Slo,
    float* __restrict__ C)
{
    if (blockIdx.y > blockIdx.x) return;     // lower triangle: mirrored from upper

    extern __shared__ __nv_bfloat16 sm[];
    __nv_bfloat16* Ahi = sm;
    __nv_bfloat16* Alo = sm + 128 * SM_STRIDE;
    __nv_bfloat16* Bhi = sm + 2 * 128 * SM_STRIDE;
    __nv_bfloat16* Blo = sm + 3 * 128 * SM_STRIDE;

    const int tid  = threadIdx.x;
    const int lane = tid & 31;
    const int wid  = tid >> 5;
    const int row0 = blockIdx.y << 7;
    const int col0 = blockIdx.x << 7;
    const bool diag = (blockIdx.x == blockIdx.y);

    for (int i = tid; i < 1024; i += 256) {
        int r = i >> 3, c = (i & 7) << 3;
        *(uint4*)(Ahi + r * SM_STRIDE + c) = *(const uint4*)(Shi + (size_t)(row0 + r) * 64 + c);
        *(uint4*)(Alo + r * SM_STRIDE + c) = *(const uint4*)(Slo + (size_t)(row0 + r) * 64 + c);
        *(uint4*)(Bhi + r * SM_STRIDE + c) = *(const uint4*)(Shi + (size_t)(col0 + r) * 64 + c);
        *(uint4*)(Blo + r * SM_STRIDE + c) = *(const uint4*)(Slo + (size_t)(col0 + r) * 64 + c);
    }
    __syncthreads();

    const int wm = (wid >> 1) << 5;
    const int wn = (wid & 1) << 6;

    float acc[2][8][4];
#pragma unroll
    for (int mt = 0; mt < 2; mt++)
#pragma unroll
        for (int nt = 0; nt < 8; nt++)
#pragma unroll
            for (int r = 0; r < 4; r++) acc[mt][nt][r] = 0.f;

    const int lr  = lane & 7;
    const int grp = lane >> 3;
    const int a_m = lr + ((grp & 1) << 3);
    const int a_k = (grp >> 1) << 3;
    const int b_n = lr + ((grp >> 1) << 3);
    const int b_k = (grp & 1) << 3;

    const uint32_t ahiB = (uint32_t)__cvta_generic_to_shared(Ahi);
    const uint32_t aloB = (uint32_t)__cvta_generic_to_shared(Alo);
    const uint32_t bhiB = (uint32_t)__cvta_generic_to_shared(Bhi);
    const uint32_t bloB = (uint32_t)__cvta_generic_to_shared(Blo);

#pragma unroll
    for (int ks = 0; ks < 4; ks++) {
        const int k0 = ks << 4;
        uint32_t ah[2][4], al[2][4];
#pragma unroll
        for (int mt = 0; mt < 2; mt++) {
            uint32_t off = (uint32_t)(((wm + (mt << 4) + a_m) * SM_STRIDE + k0 + a_k) << 1);
            LDSM_X4(ah[mt][0], ah[mt][1], ah[mt][2], ah[mt][3], ahiB + off);
            LDSM_X4(al[mt][0], al[mt][1], al[mt][2], al[mt][3], aloB + off);
        }
#pragma unroll
        for (int np = 0; np < 4; np++) {
            uint32_t off = (uint32_t)(((wn + (np << 4) + b_n) * SM_STRIDE + k0 + b_k) << 1);
            uint32_t bh[4], bl[4];
            LDSM_X4(bh[0], bh[1], bh[2], bh[3], bhiB + off);
            LDSM_X4(bl[0], bl[1], bl[2], bl[3], bloB + off);
#pragma unroll
            for (int mt = 0; mt < 2; mt++) {
                float* d0 = acc[mt][2 * np];
                float* d1 = acc[mt][2 * np + 1];
                MMA_BF16(d0, ah[mt], bh[0], bh[1]);
                MMA_BF16(d1, ah[mt], bh[2], bh[3]);
                MMA_BF16(d0, ah[mt], bl[0], bl[1]);
                MMA_BF16(d1, ah[mt], bl[2], bl[3]);
                MMA_BF16(d0, al[mt], bh[0], bh[1]);
                MMA_BF16(d1, al[mt], bh[2], bh[3]);
            }
        }
    }

    const int crow = lane >> 2;
    const int ccol = (lane & 3) << 1;

#pragma unroll
    for (int mt = 0; mt < 2; mt++) {
#pragma unroll
        for (int nt = 0; nt < 8; nt++) {
            int row = row0 + wm + (mt << 4) + crow;
            int col = col0 + wn + (nt << 3) + ccol;
            *(float2*)&C[(size_t)row * NN + col]       = make_float2(acc[mt][nt][0], acc[mt][nt][1]);
            *(float2*)&C[(size_t)(row + 8) * NN + col] = make_float2(acc[mt][nt][2], acc[mt][nt][3]);
        }
    }

    if (!diag) {
        __syncthreads();
        float* smT = reinterpret_cast<float*>(sm);   // [128][T_STRIDE]
#pragma unroll
        for (int mt = 0; mt < 2; mt++) {
#pragma unroll
            for (int nt = 0; nt < 8; nt++) {
                int rl = wm + (mt << 4) + crow;
                int cl = wn + (nt << 3) + ccol;
                smT[(cl)     * T_STRIDE + rl]     = acc[mt][nt][0];
                smT[(cl + 1) * T_STRIDE + rl]     = acc[mt][nt][1];
                smT[(cl)     * T_STRIDE + rl + 8] = acc[mt][nt][2];
                smT[(cl + 1) * T_STRIDE + rl + 8] = acc[mt][nt][3];
            }
        }
        __syncthreads();
#pragma unroll
        for (int i = tid; i < 4096; i += 256) {
            int r  = i >> 5;
            int c4 = (i & 31) << 2;
            float4 v = *(float4*)&smT[r * T_STRIDE + c4];
            *(float4*)&C[(size_t)(col0 + r) * NN + row0 + c4] = v;
        }
    }
}

// ---------------- GCN aggregation ----------------
template<int F, int RELU, int HAS_BIAS>
__global__ void __launch_bounds__(256) aggregate_kernel(
    const float* __restrict__ h, const float* __restrict__ bias,
    float* __restrict__ out)
{
    constexpr int VPT = F / 32;
    const int gw   = (blockIdx.x * 256 + threadIdx.x) >> 5;
    const int lane = threadIdx.x & 31;
    if (gw >= NN) return;

    float acc[VPT];
    const float di = g_deg_inv[gw];
    const float* hn = h + (size_t)gw * F;
#pragma unroll
    for (int i = 0; i < VPT; i++) {
        acc[i] = hn[(i << 5) + lane] * di;
        if (HAS_BIAS) acc[i] += bias[(i << 5) + lane];
    }

    int e = g_off[gw];
    const int e1 = g_off[gw + 1];
    for (; e + 1 < e1; e += 2) {
        int   s0 = g_csr_src[e],     s1 = g_csr_src[e + 1];
        float w0 = g_csr_norm[e],    w1 = g_csr_norm[e + 1];
        const float* p0 = h + (size_t)s0 * F;
        const float* p1 = h + (size_t)s1 * F;
#pragma unroll
        for (int i = 0; i < VPT; i++) acc[i] += p0[(i << 5) + lane] * w0;
#pragma unroll
        for (int i = 0; i < VPT; i++) acc[i] += p1[(i << 5) + lane] * w1;
    }
    if (e < e1) {
        int s = g_csr_src[e];
        float w = g_csr_norm[e];
        const float* p = h + (size_t)s * F;
#pragma unroll
        for (int i = 0; i < VPT; i++) acc[i] += p[(i << 5) + lane] * w;
    }
#pragma unroll
    for (int i = 0; i < VPT; i++) {
        float v = acc[i];
        if (RELU) v = fmaxf(v, 0.f);
        out[(size_t)gw * F + (i << 5) + lane] = v;
    }
}

// ---------------- launch ----------------
extern "C" void kernel_launch(void* const* d_in, const int* in_sizes, int n_in,
                              void* d_out, int out_size)
{
    const float* x    = (const float*)d_in[0];
    const int*   ei   = (const int*)d_in[1];     // int32 on device
    const float* W_e1 = (const float*)d_in[2];
    const float* b_e1 = (const float*)d_in[3];
    const float* W_e2 = (const float*)d_in[4];
    const float* b_e2 = (const float*)d_in[5];
    const float* W_a1 = (const float*)d_in[6];
    const float* b_a1 = (const float*)d_in[7];
    const float* W_a2 = (const float*)d_in[8];
    const float* b_a2 = (const float*)d_in[9];
    const float* W_s  = (const float*)d_in[10];
    const float* b_s  = (const float*)d_in[11];

    float* out   = (float*)d_out;
    float* x_hat = out;                                 // [NN, 256]
    float* a_hat = out + (size_t)NN * 256;              // [NN, NN]
    float* zout  = a_hat + (size_t)NN * NN;             // [NN, 64]

    float *p_tmp, *p_h1, *p_a;
    __nv_bfloat16 *p_shi, *p_slo;
    cudaGetSymbolAddress((void**)&p_tmp, g_tmp);
    cudaGetSymbolAddress((void**)&p_h1,  g_h1);
    cudaGetSymbolAddress((void**)&p_a,   g_a);
    cudaGetSymbolAddress((void**)&p_shi, g_s_hi);
    cudaGetSymbolAddress((void**)&p_slo, g_s_lo);

    const int gemm_smem = (128 + 128 + 64 + 64) * SM_STRIDE * 2;   // 55296 B
    const int syrk_smem = 4 * 128 * SM_STRIDE * 2;                 // 73728 B
    const int scan_smem = (NN + 32) * 4;                           // 49280 B

    static cudaStream_t s_side = nullptr;
    static cudaEvent_t  ev_fork, ev_l1, ev_zagg, ev_side_done;
    if (!s_side) {
        cudaStreamCreateWithFlags(&s_side, cudaStreamNonBlocking);
        cudaEventCreateWithFlags(&ev_fork,      cudaEventDisableTiming);
        cudaEventCreateWithFlags(&ev_l1,        cudaEventDisableTiming);
        cudaEventCreateWithFlags(&ev_zagg,      cudaEventDisableTiming);
        cudaEventCreateWithFlags(&ev_side_done, cudaEventDisableTiming);
        cudaFuncSetAttribute(gemm_mma_kernel<0,0,0>, cudaFuncAttributeMaxDynamicSharedMemorySize, gemm_smem);
        cudaFuncSetAttribute(gemm_mma_kernel<1,0,1>, cudaFuncAttributeMaxDynamicSharedMemorySize, gemm_smem);
        cudaFuncSetAttribute(gemm_mma_kernel<1,1,1>, cudaFuncAttributeMaxDynamicSharedMemorySize, gemm_smem);
        cudaFuncSetAttribute(gemm_mma_kernel<0,0,1>, cudaFuncAttributeMaxDynamicSharedMemorySize, gemm_smem);
        cudaFuncSetAttribute(syrk_mma_kernel, cudaFuncAttributeMaxDynamicSharedMemorySize, syrk_smem);
        cudaFuncSetAttribute(k_scan, cudaFuncAttributeMaxDynamicSharedMemorySize, scan_smem);
    }

    // ---- fork: side stream runs the encoder-L1 GEMM while main builds CSR ----
    cudaEventRecord(ev_fork, 0);
    cudaStreamWaitEvent(s_side, ev_fork, 0);

    gemm_mma_kernel<0,0,0><<<dim3(2, 96), 256, gemm_smem, s_side>>>(
        x, W_e1, nullptr, p_tmp, nullptr, nullptr, 256, 128);
    cudaEventRecord(ev_l1, s_side);

    // main: CSR build (int atomics only; 2 edges/thread)
    k_init <<<48,  256>>>();
    k_count<<<768, 256>>>(ei);
    k_scan <<<1,   1024, scan_smem>>>();
    k_fill <<<768, 256>>>(ei);

    cudaStreamWaitEvent(0, ev_l1, 0);
    aggregate_kernel<128, 1, 1><<<1536, 256>>>(p_tmp, b_e1, p_h1);

    gemm_mma_kernel<0,0,0><<<dim3(1, 96), 256, gemm_smem>>>(p_h1, W_e2, nullptr, p_tmp, nullptr, nullptr, 128, 64);
    aggregate_kernel<64, 1, 1><<<1536, 256>>>(p_tmp, b_e2, zout);

    // zagg = agg(z) (shared by both decoder branches; agg is linear)
    aggregate_kernel<64, 0, 0><<<1536, 256>>>(zout, nullptr, p_tmp);
    cudaEventRecord(ev_zagg, 0);

    // ---- main stream: structure branch (long pole): s GEMM -> syrk ----
    gemm_mma_kernel<1,1,1><<<dim3(1, 96), 256, gemm_smem>>>(p_tmp, W_s, b_s, nullptr, p_shi, p_slo, 64, 64);
    syrk_mma_kernel<<<dim3(96, 96), 256, syrk_smem>>>(p_shi, p_slo, a_hat);

    // ---- side stream: attribute branch (hidden under syrk) ----
    cudaStreamWaitEvent(s_side, ev_zagg, 0);
    gemm_mma_kernel<1,0,1><<<dim3(2, 96), 256, gemm_smem, s_side>>>(
        p_tmp, W_a1, b_a1, p_a, nullptr, nullptr, 64, 128);
    aggregate_kernel<128, 0, 0><<<1536, 256, 0, s_side>>>(p_a, nullptr, p_h1);
    gemm_mma_kernel<0,0,1><<<dim3(4, 96), 256, gemm_smem, s_side>>>(
        p_h1, W_a2, b_a2, x_hat, nullptr, nullptr, 128, 256);
    cudaEventRecord(ev_side_done, s_side);

    cudaStreamWaitEvent(0, ev_side_done, 0);
}

// round 14
// speedup vs baseline: 1.2538x; 1.0317x over previous
#include <cuda_runtime.h>
#include <cuda_fp16.h>
#include <cuda_bf16.h>
#include <cstdint>

#define NN 12288
#define EE 393216
#define SM_STRIDE 72   // 16-bit elems per row (144B; 144 mod 128 = 16 -> conflict-free)
#define T_STRIDE 132   // fp32 transpose staging stride (128+4)

// ---------------- scratch (static device globals; no allocation) ----------------
static __device__ float g_tmp[NN * 256];
static __device__ float g_h1 [NN * 128];
static __device__ float g_a  [NN * 128];
static __device__ __half g_s_hi [NN * 64];
static __device__ __half g_s_mid[NN * 64];   // fp16(hi + 2*lo)

static __device__ int   g_cnt[NN];
static __device__ int   g_cur[NN];
static __device__ int   g_off[NN + 1];
static __device__ int   g_csr_src[EE];
static __device__ float g_csr_norm[EE];
static __device__ float g_dinv_sqrt[NN];
static __device__ float g_deg_inv[NN];

// ---------------- CSR construction ----------------
__global__ void k_init() {
    int i = blockIdx.x * blockDim.x + threadIdx.x;
    if (i < NN) g_cnt[i] = 0;
}

// edge_index is int32 on device (JAX x64 disabled downcasts jnp.int64).
__global__ void k_count(const int* __restrict__ ei) {
    int e2 = blockIdx.x * blockDim.x + threadIdx.x;
    if (e2 < EE / 2) {
        int2 d = *(const int2*)&ei[EE + 2 * e2];
        if (d.x >= 0 && d.x < NN) atomicAdd(&g_cnt[d.x], 1);
        if (d.y >= 0 && d.y < NN) atomicAdd(&g_cnt[d.y], 1);
    }
}

// fused: coalesced degree terms + g_cur zero + exclusive prefix sum via smem staging
__global__ void k_scan() {
    extern __shared__ int sdyn[];
    int* scnt = sdyn;            // [NN]
    int* wpre = sdyn + NN;       // [32]
    const int t = threadIdx.x;
    const int lane = t & 31, warp = t >> 5;

#pragma unroll
    for (int i = 0; i < 12; i++) {
        int idx = t + (i << 10);
        int c = g_cnt[idx];
        scnt[idx] = c;
        float dv = rsqrtf((float)(c + 1));      // +1 self loop
        g_dinv_sqrt[idx] = dv;
        g_deg_inv[idx]   = dv * dv;
        g_cur[idx] = 0;
    }
    __syncthreads();

    const int base = t * 12;
    int loc[12];
    int s = 0;
#pragma unroll
    for (int i = 0; i < 12; i++) { loc[i] = s; s += scnt[base + i]; }

    int inc = s;
#pragma unroll
    for (int o = 1; o < 32; o <<= 1) {
        int v = __shfl_up_sync(0xFFFFFFFFu, inc, o);
        if (lane >= o) inc += v;
    }
    if (lane == 31) wpre[warp] = inc;
    __syncthreads();
    if (warp == 0) {
        int v = wpre[lane];
        int iv = v;
#pragma unroll
        for (int o = 1; o < 32; o <<= 1) {
            int u = __shfl_up_sync(0xFFFFFFFFu, iv, o);
            if (lane >= o) iv += u;
        }
        wpre[lane] = iv - v;
    }
    __syncthreads();
    const int pre = wpre[warp] + inc - s;

#pragma unroll
    for (int i = 0; i < 12; i++) scnt[base + i] = pre + loc[i];
    __syncthreads();
#pragma unroll
    for (int i = 0; i < 12; i++) {
        int idx = t + (i << 10);
        g_off[idx] = scnt[idx];
    }
    if (t == 1023) g_off[NN] = pre + s;
}

__global__ void k_fill(const int* __restrict__ ei) {
    int e2 = blockIdx.x * blockDim.x + threadIdx.x;
    if (e2 < EE / 2) {
        int2 sv = *(const int2*)&ei[2 * e2];
        int2 dv = *(const int2*)&ei[EE + 2 * e2];
        if (sv.x >= 0 && sv.x < NN && dv.x >= 0 && dv.x < NN) {
            int pos = g_off[dv.x] + atomicAdd(&g_cur[dv.x], 1);
            g_csr_src[pos]  = sv.x;
            g_csr_norm[pos] = g_dinv_sqrt[sv.x] * g_dinv_sqrt[dv.x];
        }
        if (sv.y >= 0 && sv.y < NN && dv.y >= 0 && dv.y < NN) {
            int pos = g_off[dv.y] + atomicAdd(&g_cur[dv.y], 1);
            g_csr_src[pos]  = sv.y;
            g_csr_norm[pos] = g_dinv_sqrt[sv.y] * g_dinv_sqrt[dv.y];
        }
    }
}

// ---------------- mma helpers ----------------
#define MMA_BF16(d, a, b0, b1)                                                     \
    asm volatile("mma.sync.aligned.m16n8k16.row.col.f32.bf16.bf16.f32 "            \
                 "{%0,%1,%2,%3}, {%4,%5,%6,%7}, {%8,%9}, {%0,%1,%2,%3};"           \
                 : "+f"((d)[0]), "+f"((d)[1]), "+f"((d)[2]), "+f"((d)[3])          \
                 : "r"((a)[0]), "r"((a)[1]), "r"((a)[2]), "r"((a)[3]),             \
                   "r"(b0), "r"(b1))

#define MMA_F16(d, a, b0, b1)                                                      \
    asm volatile("mma.sync.aligned.m16n8k16.row.col.f32.f16.f16.f32 "              \
                 "{%0,%1,%2,%3}, {%4,%5,%6,%7}, {%8,%9}, {%0,%1,%2,%3};"           \
                 : "+f"((d)[0]), "+f"((d)[1]), "+f"((d)[2]), "+f"((d)[3])          \
                 : "r"((a)[0]), "r"((a)[1]), "r"((a)[2]), "r"((a)[3]),             \
                   "r"(b0), "r"(b1))

#define LDSM_X4(r0, r1, r2, r3, addr)                                              \
    asm volatile("ldmatrix.sync.aligned.m8n8.x4.shared.b16 {%0,%1,%2,%3}, [%4];"   \
                 : "=r"(r0), "=r"(r1), "=r"(r2), "=r"(r3) : "r"(addr))

#define LDSM_X4_T(r0, r1, r2, r3, addr)                                                \
    asm volatile("ldmatrix.sync.aligned.m8n8.x4.trans.shared.b16 {%0,%1,%2,%3}, [%4];" \
                 : "=r"(r0), "=r"(r1), "=r"(r2), "=r"(r3) : "r"(addr))

// ---------------- general GEMM on tensor cores with fp32->bf16 hi/lo split ----------------
// SPLIT epilogue emits fp16 (hi, mid=fp16(hi+2*lo)) operands for the 2-product syrk.
template<int RELU, int SPLIT, int HAS_BIAS>
__global__ void __launch_bounds__(256) gemm_mma_kernel(
    const float* __restrict__ A, const float* __restrict__ B,
    const float* __restrict__ bias, float* __restrict__ C,
    __half* __restrict__ Chi, __half* __restrict__ Cmid,
    int K, int F)
{
    extern __shared__ __nv_bfloat16 sm[];
    __nv_bfloat16* Ahi = sm;
    __nv_bfloat16* Alo = Ahi + 128 * SM_STRIDE;
    __nv_bfloat16* Bhi = Alo + 128 * SM_STRIDE;
    __nv_bfloat16* Blo = Bhi + 64 * SM_STRIDE;

    const int tid  = threadIdx.x;
    const int lane = tid & 31;
    const int wid  = tid >> 5;
    const int row0 = blockIdx.y << 7;
    const int col0 = blockIdx.x << 6;

    const int wm = (wid >> 1) << 5;
    const int wn = (wid & 1) << 5;

    float acc[2][4][4];
#pragma unroll
    for (int mt = 0; mt < 2; mt++)
#pragma unroll
        for (int nt = 0; nt < 4; nt++)
#pragma unroll
            for (int r = 0; r < 4; r++) acc[mt][nt][r] = 0.f;

    const int lr  = lane & 7;
    const int grp = lane >> 3;
    const int a_m = lr + ((grp & 1) << 3);
    const int a_k = (grp >> 1) << 3;
    const int bt_k = lr + ((grp & 1) << 3);
    const int bt_n = (grp >> 1) << 3;

    const uint32_t ahiB = (uint32_t)__cvta_generic_to_shared(Ahi);
    const uint32_t aloB = (uint32_t)__cvta_generic_to_shared(Alo);
    const uint32_t bhiB = (uint32_t)__cvta_generic_to_shared(Bhi);
    const uint32_t bloB = (uint32_t)__cvta_generic_to_shared(Blo);

    for (int k0 = 0; k0 < K; k0 += 64) {
        if (k0) __syncthreads();
#pragma unroll
        for (int i = tid; i < 2048; i += 256) {
            int r = i >> 4, c = (i & 15) << 2;
            float4 v = *(const float4*)&A[(size_t)(row0 + r) * K + k0 + c];
            __nv_bfloat162 h01 = __floats2bfloat162_rn(v.x, v.y);
            __nv_bfloat162 h23 = __floats2bfloat162_rn(v.z, v.w);
            __nv_bfloat162 l01 = __floats2bfloat162_rn(v.x - __bfloat162float(h01.x),
                                                       v.y - __bfloat162float(h01.y));
            __nv_bfloat162 l23 = __floats2bfloat162_rn(v.z - __bfloat162float(h23.x),
                                                       v.w - __bfloat162float(h23.y));
            *(__nv_bfloat162*)&Ahi[r * SM_STRIDE + c]     = h01;
            *(__nv_bfloat162*)&Ahi[r * SM_STRIDE + c + 2] = h23;
            *(__nv_bfloat162*)&Alo[r * SM_STRIDE + c]     = l01;
            *(__nv_bfloat162*)&Alo[r * SM_STRIDE + c + 2] = l23;
        }
#pragma unroll
        for (int i = tid; i < 1024; i += 256) {
            int r = i >> 4, c = (i & 15) << 2;
            float4 v = *(const float4*)&B[(size_t)(k0 + r) * F + col0 + c];
            __nv_bfloat162 h01 = __floats2bfloat162_rn(v.x, v.y);
            __nv_bfloat162 h23 = __floats2bfloat162_rn(v.z, v.w);
            __nv_bfloat162 l01 = __floats2bfloat162_rn(v.x - __bfloat162float(h01.x),
                                                       v.y - __bfloat162float(h01.y));
            __nv_bfloat162 l23 = __floats2bfloat162_rn(v.z - __bfloat162float(h23.x),
                                                       v.w - __bfloat162float(h23.y));
            *(__nv_bfloat162*)&Bhi[r * SM_STRIDE + c]     = h01;
            *(__nv_bfloat162*)&Bhi[r * SM_STRIDE + c + 2] = h23;
            *(__nv_bfloat162*)&Blo[r * SM_STRIDE + c]     = l01;
            *(__nv_bfloat162*)&Blo[r * SM_STRIDE + c + 2] = l23;
        }
        __syncthreads();

#pragma unroll
        for (int ks = 0; ks < 4; ks++) {
            const int kk = ks << 4;
            uint32_t ah[2][4], al[2][4];
#pragma unroll
            for (int mt = 0; mt < 2; mt++) {
                uint32_t off = (uint32_t)(((wm + (mt << 4) + a_m) * SM_STRIDE + kk + a_k) << 1);
                LDSM_X4(ah[mt][0], ah[mt][1], ah[mt][2], ah[mt][3], ahiB + off);
                LDSM_X4(al[mt][0], al[mt][1], al[mt][2], al[mt][3], aloB + off);
            }
#pragma unroll
            for (int np = 0; np < 2; np++) {
                uint32_t off = (uint32_t)(((kk + bt_k) * SM_STRIDE + wn + (np << 4) + bt_n) << 1);
                uint32_t bh[4], bl[4];
                LDSM_X4_T(bh[0], bh[1], bh[2], bh[3], bhiB + off);
                LDSM_X4_T(bl[0], bl[1], bl[2], bl[3], bloB + off);
#pragma unroll
                for (int mt = 0; mt < 2; mt++) {
                    float* d0 = acc[mt][2 * np];
                    float* d1 = acc[mt][2 * np + 1];
                    MMA_BF16(d0, ah[mt], bh[0], bh[1]);
                    MMA_BF16(d1, ah[mt], bh[2], bh[3]);
                    MMA_BF16(d0, ah[mt], bl[0], bl[1]);
                    MMA_BF16(d1, ah[mt], bl[2], bl[3]);
                    MMA_BF16(d0, al[mt], bh[0], bh[1]);
                    MMA_BF16(d1, al[mt], bh[2], bh[3]);
                }
            }
        }
    }

    const int crow = lane >> 2;
    const int ccol = (lane & 3) << 1;
#pragma unroll
    for (int mt = 0; mt < 2; mt++) {
#pragma unroll
        for (int nt = 0; nt < 4; nt++) {
            int row = row0 + wm + (mt << 4) + crow;
            int col = col0 + wn + (nt << 3) + ccol;
            float v0 = acc[mt][nt][0], v1 = acc[mt][nt][1];
            float v2 = acc[mt][nt][2], v3 = acc[mt][nt][3];
            if (HAS_BIAS) {
                float2 bb = *(const float2*)&bias[col];
                v0 += bb.x; v1 += bb.y; v2 += bb.x; v3 += bb.y;
            }
            if (RELU) {
                v0 = fmaxf(v0, 0.f); v1 = fmaxf(v1, 0.f);
                v2 = fmaxf(v2, 0.f); v3 = fmaxf(v3, 0.f);
            }
            if (SPLIT) {
                // fp16 hi; mid = fp16(hi + 2*(v - hi))  (2-product syrk operands)
                __half2 h0 = __floats2half2_rn(v0, v1);
                __half2 h1v = __floats2half2_rn(v2, v3);
                float h0x = __low2float(h0),  h0y = __high2float(h0);
                float h1x = __low2float(h1v), h1y = __high2float(h1v);
                __half2 m0 = __floats2half2_rn(h0x + 2.f * (v0 - h0x),
                                               h0y + 2.f * (v1 - h0y));
                __half2 m1 = __floats2half2_rn(h1x + 2.f * (v2 - h1x),
                                               h1y + 2.f * (v3 - h1y));
                *(__half2*)&Chi [(size_t)row * F + col]       = h0;
                *(__half2*)&Chi [(size_t)(row + 8) * F + col] = h1v;
                *(__half2*)&Cmid[(size_t)row * F + col]       = m0;
                *(__half2*)&Cmid[(size_t)(row + 8) * F + col] = m1;
            } else {
                *(float2*)&C[(size_t)row * F + col]       = make_float2(v0, v1);
                *(float2*)&C[(size_t)(row + 8) * F + col] = make_float2(v2, v3);
            }
        }
    }
}

// ---------------- symmetric syrk: fp16 2-product symmetrized hi/mid ----------------
// C = 0.5*(hi.mid^T + mid.hi^T) = hi.hi^T + hi.lo^T + lo.hi^T  (+O(2^-12/sqrt(K)))
__global__ void __launch_bounds__(256, 2) syrk_mma_kernel(
    const __half* __restrict__ Shi,
    const __half* __restrict__ Smid,
    float* __restrict__ C)
{
    if (blockIdx.y > blockIdx.x) return;     // lower triangle: mirrored from upper

    extern __shared__ __half smh[];
    __half* Ahi = smh;
    __half* Ami = smh + 128 * SM_STRIDE;
    __half* Bhi = smh + 2 * 128 * SM_STRIDE;
    __half* Bmi = smh + 3 * 128 * SM_STRIDE;

    const int tid  = threadIdx.x;
    const int lane = tid & 31;
    const int wid  = tid >> 5;
    const int row0 = blockIdx.y << 7;
    const int col0 = blockIdx.x << 7;
    const bool diag = (blockIdx.x == blockIdx.y);

    for (int i = tid; i < 1024; i += 256) {
        int r = i >> 3, c = (i & 7) << 3;
        *(uint4*)(Ahi + r * SM_STRIDE + c) = *(const uint4*)(Shi  + (size_t)(row0 + r) * 64 + c);
        *(uint4*)(Ami + r * SM_STRIDE + c) = *(const uint4*)(Smid + (size_t)(row0 + r) * 64 + c);
        *(uint4*)(Bhi + r * SM_STRIDE + c) = *(const uint4*)(Shi  + (size_t)(col0 + r) * 64 + c);
        *(uint4*)(Bmi + r * SM_STRIDE + c) = *(const uint4*)(Smid + (size_t)(col0 + r) * 64 + c);
    }
    __syncthreads();

    const int wm = (wid >> 1) << 5;
    const int wn = (wid & 1) << 6;

    float acc[2][8][4];
#pragma unroll
    for (int mt = 0; mt < 2; mt++)
#pragma unroll
        for (int nt = 0; nt < 8; nt++)
#pragma unroll
            for (int r = 0; r < 4; r++) acc[mt][nt][r] = 0.f;

    const int lr  = lane & 7;
    const int grp = lane >> 3;
    const int a_m = lr + ((grp & 1) << 3);
    const int a_k = (grp >> 1) << 3;
    const int b_n = lr + ((grp >> 1) << 3);
    const int b_k = (grp & 1) << 3;

    const uint32_t ahiB = (uint32_t)__cvta_generic_to_shared(Ahi);
    const uint32_t amiB = (uint32_t)__cvta_generic_to_shared(Ami);
    const uint32_t bhiB = (uint32_t)__cvta_generic_to_shared(Bhi);
    const uint32_t bmiB = (uint32_t)__cvta_generic_to_shared(Bmi);

#pragma unroll
    for (int ks = 0; ks < 4; ks++) {
        const int k0 = ks << 4;
        uint32_t ah[2][4], am[2][4];
#pragma unroll
        for (int mt = 0; mt < 2; mt++) {
            uint32_t off = (uint32_t)(((wm + (mt << 4) + a_m) * SM_STRIDE + k0 + a_k) << 1);
            LDSM_X4(ah[mt][0], ah[mt][1], ah[mt][2], ah[mt][3], ahiB + off);
            LDSM_X4(am[mt][0], am[mt][1], am[mt][2], am[mt][3], amiB + off);
        }
#pragma unroll
        for (int np = 0; np < 4; np++) {
            uint32_t off = (uint32_t)(((wn + (np << 4) + b_n) * SM_STRIDE + k0 + b_k) << 1);
            uint32_t bh[4], bm[4];
            LDSM_X4(bh[0], bh[1], bh[2], bh[3], bhiB + off);
            LDSM_X4(bm[0], bm[1], bm[2], bm[3], bmiB + off);
#pragma unroll
            for (int mt = 0; mt < 2; mt++) {
                float* d0 = acc[mt][2 * np];
                float* d1 = acc[mt][2 * np + 1];
                MMA_F16(d0, ah[mt], bm[0], bm[1]);   // hi . mid^T
                MMA_F16(d1, ah[mt], bm[2], bm[3]);
                MMA_F16(d0, am[mt], bh[0], bh[1]);   // mid . hi^T
                MMA_F16(d1, am[mt], bh[2], bh[3]);
            }
        }
    }

    // scale by 0.5 (symmetrized average)
#pragma unroll
    for (int mt = 0; mt < 2; mt++)
#pragma unroll
        for (int nt = 0; nt < 8; nt++)
#pragma unroll
            for (int r = 0; r < 4; r++) acc[mt][nt][r] *= 0.5f;

    const int crow = lane >> 2;
    const int ccol = (lane & 3) << 1;

#pragma unroll
    for (int mt = 0; mt < 2; mt++) {
#pragma unroll
        for (int nt = 0; nt < 8; nt++) {
            int row = row0 + wm + (mt << 4) + crow;
            int col = col0 + wn + (nt << 3) + ccol;
            *(float2*)&C[(size_t)row * NN + col]       = make_float2(acc[mt][nt][0], acc[mt][nt][1]);
            *(float2*)&C[(size_t)(row + 8) * NN + col] = make_float2(acc[mt][nt][2], acc[mt][nt][3]);
        }
    }

    if (!diag) {
        __syncthreads();
        float* smT = reinterpret_cast<float*>(smh);   // [128][T_STRIDE]
#pragma unroll
        for (int mt = 0; mt < 2; mt++) {
#pragma unroll
            for (int nt = 0; nt < 8; nt++) {
                int rl = wm + (mt << 4) + crow;
                int cl = wn + (nt << 3) + ccol;
                smT[(cl)     * T_STRIDE + rl]     = acc[mt][nt][0];
                smT[(cl + 1) * T_STRIDE + rl]     = acc[mt][nt][1];
                smT[(cl)     * T_STRIDE + rl + 8] = acc[mt][nt][2];
                smT[(cl + 1) * T_STRIDE + rl + 8] = acc[mt][nt][3];
            }
        }
        __syncthreads();
#pragma unroll
        for (int i = tid; i < 4096; i += 256) {
            int r  = i >> 5;
            int c4 = (i & 31) << 2;
            float4 v = *(float4*)&smT[r * T_STRIDE + c4];
            *(float4*)&C[(size_t)(col0 + r) * NN + row0 + c4] = v;
        }
    }
}

// ---------------- GCN aggregation ----------------
template<int F, int RELU, int HAS_BIAS>
__global__ void __launch_bounds__(256) aggregate_kernel(
    const float* __restrict__ h, const float* __restrict__ bias,
    float* __restrict__ out)
{
    constexpr int VPT = F / 32;
    const int gw   = (blockIdx.x * 256 + threadIdx.x) >> 5;
    const int lane = threadIdx.x & 31;
    if (gw >= NN) return;

    float acc[VPT];
    const float di = g_deg_inv[gw];
    const float* hn = h + (size_t)gw * F;
#pragma unroll
    for (int i = 0; i < VPT; i++) {
        acc[i] = hn[(i << 5) + lane] * di;
        if (HAS_BIAS) acc[i] += bias[(i << 5) + lane];
    }

    int e = g_off[gw];
    const int e1 = g_off[gw + 1];
    for (; e + 1 < e1; e += 2) {
        int   s0 = g_csr_src[e],     s1 = g_csr_src[e + 1];
        float w0 = g_csr_norm[e],    w1 = g_csr_norm[e + 1];
        const float* p0 = h + (size_t)s0 * F;
        const float* p1 = h + (size_t)s1 * F;
#pragma unroll
        for (int i = 0; i < VPT; i++) acc[i] += p0[(i << 5) + lane] * w0;
#pragma unroll
        for (int i = 0; i < VPT; i++) acc[i] += p1[(i << 5) + lane] * w1;
    }
    if (e < e1) {
        int s = g_csr_src[e];
        float w = g_csr_norm[e];
        const float* p = h + (size_t)s * F;
#pragma unroll
        for (int i = 0; i < VPT; i++) acc[i] += p[(i << 5) + lane] * w;
    }
#pragma unroll
    for (int i = 0; i < VPT; i++) {
        float v = acc[i];
        if (RELU) v = fmaxf(v, 0.f);
        out[(size_t)gw * F + (i << 5) + lane] = v;
    }
}

// ---------------- launch ----------------
extern "C" void kernel_launch(void* const* d_in, const int* in_sizes, int n_in,
                              void* d_out, int out_size)
{
    const float* x    = (const float*)d_in[0];
    const int*   ei   = (const int*)d_in[1];     // int32 on device
    const float* W_e1 = (const float*)d_in[2];
    const float* b_e1 = (const float*)d_in[3];
    const float* W_e2 = (const float*)d_in[4];
    const float* b_e2 = (const float*)d_in[5];
    const float* W_a1 = (const float*)d_in[6];
    const float* b_a1 = (const float*)d_in[7];
    const float* W_a2 = (const float*)d_in[8];
    const float* b_a2 = (const float*)d_in[9];
    const float* W_s  = (const float*)d_in[10];
    const float* b_s  = (const float*)d_in[11];

    float* out   = (float*)d_out;
    float* x_hat = out;                                 // [NN, 256]
    float* a_hat = out + (size_t)NN * 256;              // [NN, NN]
    float* zout  = a_hat + (size_t)NN * NN;             // [NN, 64]

    float *p_tmp, *p_h1, *p_a;
    __half *p_shi, *p_smid;
    cudaGetSymbolAddress((void**)&p_tmp,  g_tmp);
    cudaGetSymbolAddress((void**)&p_h1,   g_h1);
    cudaGetSymbolAddress((void**)&p_a,    g_a);
    cudaGetSymbolAddress((void**)&p_shi,  g_s_hi);
    cudaGetSymbolAddress((void**)&p_smid, g_s_mid);

    const int gemm_smem = (128 + 128 + 64 + 64) * SM_STRIDE * 2;   // 55296 B
    const int syrk_smem = 4 * 128 * SM_STRIDE * 2;                 // 73728 B
    const int scan_smem = (NN + 32) * 4;                           // 49280 B

    static cudaStream_t s_side = nullptr;
    static cudaEvent_t  ev_fork, ev_l1, ev_zagg, ev_side_done;
    if (!s_side) {
        cudaStreamCreateWithFlags(&s_side, cudaStreamNonBlocking);
        cudaEventCreateWithFlags(&ev_fork,      cudaEventDisableTiming);
        cudaEventCreateWithFlags(&ev_l1,        cudaEventDisableTiming);
        cudaEventCreateWithFlags(&ev_zagg,      cudaEventDisableTiming);
        cudaEventCreateWithFlags(&ev_side_done, cudaEventDisableTiming);
        cudaFuncSetAttribute(gemm_mma_kernel<0,0,0>, cudaFuncAttributeMaxDynamicSharedMemorySize, gemm_smem);
        cudaFuncSetAttribute(gemm_mma_kernel<1,0,1>, cudaFuncAttributeMaxDynamicSharedMemorySize, gemm_smem);
        cudaFuncSetAttribute(gemm_mma_kernel<1,1,1>, cudaFuncAttributeMaxDynamicSharedMemorySize, gemm_smem);
        cudaFuncSetAttribute(gemm_mma_kernel<0,0,1>, cudaFuncAttributeMaxDynamicSharedMemorySize, gemm_smem);
        cudaFuncSetAttribute(syrk_mma_kernel, cudaFuncAttributeMaxDynamicSharedMemorySize, syrk_smem);
        cudaFuncSetAttribute(k_scan, cudaFuncAttributeMaxDynamicSharedMemorySize, scan_smem);
    }

    // ---- fork: side stream runs the encoder-L1 GEMM while main builds CSR ----
    cudaEventRecord(ev_fork, 0);
    cudaStreamWaitEvent(s_side, ev_fork, 0);

    gemm_mma_kernel<0,0,0><<<dim3(2, 96), 256, gemm_smem, s_side>>>(
        x, W_e1, nullptr, p_tmp, nullptr, nullptr, 256, 128);
    cudaEventRecord(ev_l1, s_side);

    // main: CSR build (int atomics only; 2 edges/thread)
    k_init <<<48,  256>>>();
    k_count<<<768, 256>>>(ei);
    k_scan <<<1,   1024, scan_smem>>>();
    k_fill <<<768, 256>>>(ei);

    cudaStreamWaitEvent(0, ev_l1, 0);
    aggregate_kernel<128, 1, 1><<<1536, 256>>>(p_tmp, b_e1, p_h1);

    gemm_mma_kernel<0,0,0><<<dim3(1, 96), 256, gemm_smem>>>(p_h1, W_e2, nullptr, p_tmp, nullptr, nullptr, 128, 64);
    aggregate_kernel<64, 1, 1><<<1536, 256>>>(p_tmp, b_e2, zout);

    // zagg = agg(z) (shared by both decoder branches; agg is linear)
    aggregate_kernel<64, 0, 0><<<1536, 256>>>(zout, nullptr, p_tmp);
    cudaEventRecord(ev_zagg, 0);

    // ---- main stream: structure branch (long pole): s GEMM -> syrk ----
    gemm_mma_kernel<1,1,1><<<dim3(1, 96), 256, gemm_smem>>>(p_tmp, W_s, b_s, nullptr, p_shi, p_smid, 64, 64);
    syrk_mma_kernel<<<dim3(96, 96), 256, syrk_smem>>>(p_shi, p_smid, a_hat);

    // ---- side stream: attribute branch (hidden under syrk) ----
    cudaStreamWaitEvent(s_side, ev_zagg, 0);
    gemm_mma_kernel<1,0,1><<<dim3(2, 96), 256, gemm_smem, s_side>>>(
        p_tmp, W_a1, b_a1, p_a, nullptr, nullptr, 64, 128);
    aggregate_kernel<128, 0, 0><<<1536, 256, 0, s_side>>>(p_a, nullptr, p_h1);
    gemm_mma_kernel<0,0,1><<<dim3(4, 96), 256, gemm_smem, s_side>>>(
        p_h1, W_a2, b_a2, x_hat, nullptr, nullptr, 128, 256);
    cudaEventRecord(ev_side_done, s_side);

    cudaStreamWaitEvent(0, ev_side_done, 0);
}

// round 15
// speedup vs baseline: 1.2638x; 1.0080x over previous
#include <cuda_runtime.h>
#include <cuda_fp16.h>
#include <cstdint>

#define NN 12288
#define EE 393216
#define SM_STRIDE 72   // 16-bit elems per row (144B; 144 mod 128 = 16 -> conflict-free)
#define T_STRIDE 132   // fp32 transpose staging stride (128+4)

// ---------------- scratch (static device globals; no allocation) ----------------
static __device__ float g_tmp[NN * 256];
static __device__ float g_h1 [NN * 128];
static __device__ float g_a  [NN * 128];
static __device__ __half g_s_hi [NN * 64];
static __device__ __half g_s_mid[NN * 64];   // fp16(hi + 2*lo)

static __device__ int   g_cnt[NN];
static __device__ int   g_cur[NN];
static __device__ int   g_off[NN + 1];
static __device__ int   g_csr_src[EE];
static __device__ float g_csr_norm[EE];
static __device__ float g_dinv_sqrt[NN];
static __device__ float g_deg_inv[NN];

// ---------------- CSR construction ----------------
__global__ void k_init() {
    int i = blockIdx.x * blockDim.x + threadIdx.x;
    if (i < NN) g_cnt[i] = 0;
}

// edge_index is int32 on device (JAX x64 disabled downcasts jnp.int64).
__global__ void k_count(const int* __restrict__ ei) {
    int e2 = blockIdx.x * blockDim.x + threadIdx.x;
    if (e2 < EE / 2) {
        int2 d = *(const int2*)&ei[EE + 2 * e2];
        if (d.x >= 0 && d.x < NN) atomicAdd(&g_cnt[d.x], 1);
        if (d.y >= 0 && d.y < NN) atomicAdd(&g_cnt[d.y], 1);
    }
}

// fused: coalesced degree terms + g_cur zero + exclusive prefix sum via smem staging
__global__ void k_scan() {
    extern __shared__ int sdyn[];
    int* scnt = sdyn;            // [NN]
    int* wpre = sdyn + NN;       // [32]
    const int t = threadIdx.x;
    const int lane = t & 31, warp = t >> 5;

#pragma unroll
    for (int i = 0; i < 12; i++) {
        int idx = t + (i << 10);
        int c = g_cnt[idx];
        scnt[idx] = c;
        float dv = rsqrtf((float)(c + 1));      // +1 self loop
        g_dinv_sqrt[idx] = dv;
        g_deg_inv[idx]   = dv * dv;
        g_cur[idx] = 0;
    }
    __syncthreads();

    const int base = t * 12;
    int loc[12];
    int s = 0;
#pragma unroll
    for (int i = 0; i < 12; i++) { loc[i] = s; s += scnt[base + i]; }

    int inc = s;
#pragma unroll
    for (int o = 1; o < 32; o <<= 1) {
        int v = __shfl_up_sync(0xFFFFFFFFu, inc, o);
        if (lane >= o) inc += v;
    }
    if (lane == 31) wpre[warp] = inc;
    __syncthreads();
    if (warp == 0) {
        int v = wpre[lane];
        int iv = v;
#pragma unroll
        for (int o = 1; o < 32; o <<= 1) {
            int u = __shfl_up_sync(0xFFFFFFFFu, iv, o);
            if (lane >= o) iv += u;
        }
        wpre[lane] = iv - v;
    }
    __syncthreads();
    const int pre = wpre[warp] + inc - s;

#pragma unroll
    for (int i = 0; i < 12; i++) scnt[base + i] = pre + loc[i];
    __syncthreads();
#pragma unroll
    for (int i = 0; i < 12; i++) {
        int idx = t + (i << 10);
        g_off[idx] = scnt[idx];
    }
    if (t == 1023) g_off[NN] = pre + s;
}

__global__ void k_fill(const int* __restrict__ ei) {
    int e2 = blockIdx.x * blockDim.x + threadIdx.x;
    if (e2 < EE / 2) {
        int2 sv = *(const int2*)&ei[2 * e2];
        int2 dv = *(const int2*)&ei[EE + 2 * e2];
        if (sv.x >= 0 && sv.x < NN && dv.x >= 0 && dv.x < NN) {
            int pos = g_off[dv.x] + atomicAdd(&g_cur[dv.x], 1);
            g_csr_src[pos]  = sv.x;
            g_csr_norm[pos] = g_dinv_sqrt[sv.x] * g_dinv_sqrt[dv.x];
        }
        if (sv.y >= 0 && sv.y < NN && dv.y >= 0 && dv.y < NN) {
            int pos = g_off[dv.y] + atomicAdd(&g_cur[dv.y], 1);
            g_csr_src[pos]  = sv.y;
            g_csr_norm[pos] = g_dinv_sqrt[sv.y] * g_dinv_sqrt[dv.y];
        }
    }
}

// ---------------- mma helpers ----------------
#define MMA_F16(d, a, b0, b1)                                                      \
    asm volatile("mma.sync.aligned.m16n8k16.row.col.f32.f16.f16.f32 "              \
                 "{%0,%1,%2,%3}, {%4,%5,%6,%7}, {%8,%9}, {%0,%1,%2,%3};"           \
                 : "+f"((d)[0]), "+f"((d)[1]), "+f"((d)[2]), "+f"((d)[3])          \
                 : "r"((a)[0]), "r"((a)[1]), "r"((a)[2]), "r"((a)[3]),             \
                   "r"(b0), "r"(b1))

#define LDSM_X4(r0, r1, r2, r3, addr)                                              \
    asm volatile("ldmatrix.sync.aligned.m8n8.x4.shared.b16 {%0,%1,%2,%3}, [%4];"   \
                 : "=r"(r0), "=r"(r1), "=r"(r2), "=r"(r3) : "r"(addr))

#define LDSM_X4_T(r0, r1, r2, r3, addr)                                                \
    asm volatile("ldmatrix.sync.aligned.m8n8.x4.trans.shared.b16 {%0,%1,%2,%3}, [%4];" \
                 : "=r"(r0), "=r"(r1), "=r"(r2), "=r"(r3) : "r"(addr))

// fp16 split: h = fp16(v); m = fp16(h + 2*(v-h));  0.5*(a_h b_m + a_m b_h) recovers
// h_a h_b + h_a l_b + l_a h_b  (validated 2-product identity)
__device__ __forceinline__ void split2_f16(float v0, float v1, __half2& h, __half2& m) {
    h = __floats2half2_rn(v0, v1);
    float hx = __low2float(h), hy = __high2float(h);
    m = __floats2half2_rn(hx + 2.f * (v0 - hx), hy + 2.f * (v1 - hy));
}

// ---------------- general GEMM on tensor cores, fp16 2-product hi/mid ----------------
// C = 0.5*(hiA.midB + midA.hiB) [+bias][relu]; SPLIT emits fp16 hi/mid of the result.
template<int RELU, int SPLIT, int HAS_BIAS>
__global__ void __launch_bounds__(256) gemm_mma_kernel(
    const float* __restrict__ A, const float* __restrict__ B,
    const float* __restrict__ bias, float* __restrict__ C,
    __half* __restrict__ Chi, __half* __restrict__ Cmid,
    int K, int F)
{
    extern __shared__ __half sm[];
    __half* Ahi = sm;
    __half* Ami = Ahi + 128 * SM_STRIDE;
    __half* Bhi = Ami + 128 * SM_STRIDE;
    __half* Bmi = Bhi + 64 * SM_STRIDE;

    const int tid  = threadIdx.x;
    const int lane = tid & 31;
    const int wid  = tid >> 5;
    const int row0 = blockIdx.y << 7;
    const int col0 = blockIdx.x << 6;

    const int wm = (wid >> 1) << 5;
    const int wn = (wid & 1) << 5;

    float acc[2][4][4];
#pragma unroll
    for (int mt = 0; mt < 2; mt++)
#pragma unroll
        for (int nt = 0; nt < 4; nt++)
#pragma unroll
            for (int r = 0; r < 4; r++) acc[mt][nt][r] = 0.f;

    const int lr  = lane & 7;
    const int grp = lane >> 3;
    const int a_m = lr + ((grp & 1) << 3);
    const int a_k = (grp >> 1) << 3;
    const int bt_k = lr + ((grp & 1) << 3);
    const int bt_n = (grp >> 1) << 3;

    const uint32_t ahiB = (uint32_t)__cvta_generic_to_shared(Ahi);
    const uint32_t amiB = (uint32_t)__cvta_generic_to_shared(Ami);
    const uint32_t bhiB = (uint32_t)__cvta_generic_to_shared(Bhi);
    const uint32_t bmiB = (uint32_t)__cvta_generic_to_shared(Bmi);

    for (int k0 = 0; k0 < K; k0 += 64) {
        if (k0) __syncthreads();
#pragma unroll
        for (int i = tid; i < 2048; i += 256) {
            int r = i >> 4, c = (i & 15) << 2;
            float4 v = *(const float4*)&A[(size_t)(row0 + r) * K + k0 + c];
            __half2 h01, m01, h23, m23;
            split2_f16(v.x, v.y, h01, m01);
            split2_f16(v.z, v.w, h23, m23);
            *(__half2*)&Ahi[r * SM_STRIDE + c]     = h01;
            *(__half2*)&Ahi[r * SM_STRIDE + c + 2] = h23;
            *(__half2*)&Ami[r * SM_STRIDE + c]     = m01;
            *(__half2*)&Ami[r * SM_STRIDE + c + 2] = m23;
        }
#pragma unroll
        for (int i = tid; i < 1024; i += 256) {
            int r = i >> 4, c = (i & 15) << 2;
            float4 v = *(const float4*)&B[(size_t)(k0 + r) * F + col0 + c];
            __half2 h01, m01, h23, m23;
            split2_f16(v.x, v.y, h01, m01);
            split2_f16(v.z, v.w, h23, m23);
            *(__half2*)&Bhi[r * SM_STRIDE + c]     = h01;
            *(__half2*)&Bhi[r * SM_STRIDE + c + 2] = h23;
            *(__half2*)&Bmi[r * SM_STRIDE + c]     = m01;
            *(__half2*)&Bmi[r * SM_STRIDE + c + 2] = m23;
        }
        __syncthreads();

#pragma unroll
        for (int ks = 0; ks < 4; ks++) {
            const int kk = ks << 4;
            uint32_t ah[2][4], am[2][4];
#pragma unroll
            for (int mt = 0; mt < 2; mt++) {
                uint32_t off = (uint32_t)(((wm + (mt << 4) + a_m) * SM_STRIDE + kk + a_k) << 1);
                LDSM_X4(ah[mt][0], ah[mt][1], ah[mt][2], ah[mt][3], ahiB + off);
                LDSM_X4(am[mt][0], am[mt][1], am[mt][2], am[mt][3], amiB + off);
            }
#pragma unroll
            for (int np = 0; np < 2; np++) {
                uint32_t off = (uint32_t)(((kk + bt_k) * SM_STRIDE + wn + (np << 4) + bt_n) << 1);
                uint32_t bh[4], bm[4];
                LDSM_X4_T(bh[0], bh[1], bh[2], bh[3], bhiB + off);
                LDSM_X4_T(bm[0], bm[1], bm[2], bm[3], bmiB + off);
#pragma unroll
                for (int mt = 0; mt < 2; mt++) {
                    float* d0 = acc[mt][2 * np];
                    float* d1 = acc[mt][2 * np + 1];
                    MMA_F16(d0, ah[mt], bm[0], bm[1]);   // hiA . midB
                    MMA_F16(d1, ah[mt], bm[2], bm[3]);
                    MMA_F16(d0, am[mt], bh[0], bh[1]);   // midA . hiB
                    MMA_F16(d1, am[mt], bh[2], bh[3]);
                }
            }
        }
    }

    const int crow = lane >> 2;
    const int ccol = (lane & 3) << 1;
#pragma unroll
    for (int mt = 0; mt < 2; mt++) {
#pragma unroll
        for (int nt = 0; nt < 4; nt++) {
            int row = row0 + wm + (mt << 4) + crow;
            int col = col0 + wn + (nt << 3) + ccol;
            float v0 = 0.5f * acc[mt][nt][0], v1 = 0.5f * acc[mt][nt][1];
            float v2 = 0.5f * acc[mt][nt][2], v3 = 0.5f * acc[mt][nt][3];
            if (HAS_BIAS) {
                float2 bb = *(const float2*)&bias[col];
                v0 += bb.x; v1 += bb.y; v2 += bb.x; v3 += bb.y;
            }
            if (RELU) {
                v0 = fmaxf(v0, 0.f); v1 = fmaxf(v1, 0.f);
                v2 = fmaxf(v2, 0.f); v3 = fmaxf(v3, 0.f);
            }
            if (SPLIT) {
                __half2 h0, m0, h1v, m1;
                split2_f16(v0, v1, h0, m0);
                split2_f16(v2, v3, h1v, m1);
                *(__half2*)&Chi [(size_t)row * F + col]       = h0;
                *(__half2*)&Chi [(size_t)(row + 8) * F + col] = h1v;
                *(__half2*)&Cmid[(size_t)row * F + col]       = m0;
                *(__half2*)&Cmid[(size_t)(row + 8) * F + col] = m1;
            } else {
                *(float2*)&C[(size_t)row * F + col]       = make_float2(v0, v1);
                *(float2*)&C[(size_t)(row + 8) * F + col] = make_float2(v2, v3);
            }
        }
    }
}

// ---------------- symmetric syrk: fp16 2-product symmetrized hi/mid (R14, validated) ----------------
__global__ void __launch_bounds__(256, 2) syrk_mma_kernel(
    const __half* __restrict__ Shi,
    const __half* __restrict__ Smid,
    float* __restrict__ C)
{
    if (blockIdx.y > blockIdx.x) return;     // lower triangle: mirrored from upper

    extern __shared__ __half smh[];
    __half* Ahi = smh;
    __half* Ami = smh + 128 * SM_STRIDE;
    __half* Bhi = smh + 2 * 128 * SM_STRIDE;
    __half* Bmi = smh + 3 * 128 * SM_STRIDE;

    const int tid  = threadIdx.x;
    const int lane = tid & 31;
    const int wid  = tid >> 5;
    const int row0 = blockIdx.y << 7;
    const int col0 = blockIdx.x << 7;
    const bool diag = (blockIdx.x == blockIdx.y);

    for (int i = tid; i < 1024; i += 256) {
        int r = i >> 3, c = (i & 7) << 3;
        *(uint4*)(Ahi + r * SM_STRIDE + c) = *(const uint4*)(Shi  + (size_t)(row0 + r) * 64 + c);
        *(uint4*)(Ami + r * SM_STRIDE + c) = *(const uint4*)(Smid + (size_t)(row0 + r) * 64 + c);
        *(uint4*)(Bhi + r * SM_STRIDE + c) = *(const uint4*)(Shi  + (size_t)(col0 + r) * 64 + c);
        *(uint4*)(Bmi + r * SM_STRIDE + c) = *(const uint4*)(Smid + (size_t)(col0 + r) * 64 + c);
    }
    __syncthreads();

    const int wm = (wid >> 1) << 5;
    const int wn = (wid & 1) << 6;

    float acc[2][8][4];
#pragma unroll
    for (int mt = 0; mt < 2; mt++)
#pragma unroll
        for (int nt = 0; nt < 8; nt++)
#pragma unroll
            for (int r = 0; r < 4; r++) acc[mt][nt][r] = 0.f;

    const int lr  = lane & 7;
    const int grp = lane >> 3;
    const int a_m = lr + ((grp & 1) << 3);
    const int a_k = (grp >> 1) << 3;
    const int b_n = lr + ((grp >> 1) << 3);
    const int b_k = (grp & 1) << 3;

    const uint32_t ahiB = (uint32_t)__cvta_generic_to_shared(Ahi);
    const uint32_t amiB = (uint32_t)__cvta_generic_to_shared(Ami);
    const uint32_t bhiB = (uint32_t)__cvta_generic_to_shared(Bhi);
    const uint32_t bmiB = (uint32_t)__cvta_generic_to_shared(Bmi);

#pragma unroll
    for (int ks = 0; ks < 4; ks++) {
        const int k0 = ks << 4;
        uint32_t ah[2][4], am[2][4];
#pragma unroll
        for (int mt = 0; mt < 2; mt++) {
            uint32_t off = (uint32_t)(((wm + (mt << 4) + a_m) * SM_STRIDE + k0 + a_k) << 1);
            LDSM_X4(ah[mt][0], ah[mt][1], ah[mt][2], ah[mt][3], ahiB + off);
            LDSM_X4(am[mt][0], am[mt][1], am[mt][2], am[mt][3], amiB + off);
        }
#pragma unroll
        for (int np = 0; np < 4; np++) {
            uint32_t off = (uint32_t)(((wn + (np << 4) + b_n) * SM_STRIDE + k0 + b_k) << 1);
            uint32_t bh[4], bm[4];
            LDSM_X4(bh[0], bh[1], bh[2], bh[3], bhiB + off);
            LDSM_X4(bm[0], bm[1], bm[2], bm[3], bmiB + off);
#pragma unroll
            for (int mt = 0; mt < 2; mt++) {
                float* d0 = acc[mt][2 * np];
                float* d1 = acc[mt][2 * np + 1];
                MMA_F16(d0, ah[mt], bm[0], bm[1]);   // hi . mid^T
                MMA_F16(d1, ah[mt], bm[2], bm[3]);
                MMA_F16(d0, am[mt], bh[0], bh[1]);   // mid . hi^T
                MMA_F16(d1, am[mt], bh[2], bh[3]);
            }
        }
    }

#pragma unroll
    for (int mt = 0; mt < 2; mt++)
#pragma unroll
        for (int nt = 0; nt < 8; nt++)
#pragma unroll
            for (int r = 0; r < 4; r++) acc[mt][nt][r] *= 0.5f;

    const int crow = lane >> 2;
    const int ccol = (lane & 3) << 1;

#pragma unroll
    for (int mt = 0; mt < 2; mt++) {
#pragma unroll
        for (int nt = 0; nt < 8; nt++) {
            int row = row0 + wm + (mt << 4) + crow;
            int col = col0 + wn + (nt << 3) + ccol;
            *(float2*)&C[(size_t)row * NN + col]       = make_float2(acc[mt][nt][0], acc[mt][nt][1]);
            *(float2*)&C[(size_t)(row + 8) * NN + col] = make_float2(acc[mt][nt][2], acc[mt][nt][3]);
        }
    }

    if (!diag) {
        __syncthreads();
        float* smT = reinterpret_cast<float*>(smh);   // [128][T_STRIDE]
#pragma unroll
        for (int mt = 0; mt < 2; mt++) {
#pragma unroll
            for (int nt = 0; nt < 8; nt++) {
                int rl = wm + (mt << 4) + crow;
                int cl = wn + (nt << 3) + ccol;
                smT[(cl)     * T_STRIDE + rl]     = acc[mt][nt][0];
                smT[(cl + 1) * T_STRIDE + rl]     = acc[mt][nt][1];
                smT[(cl)     * T_STRIDE + rl + 8] = acc[mt][nt][2];
                smT[(cl + 1) * T_STRIDE + rl + 8] = acc[mt][nt][3];
            }
        }
        __syncthreads();
#pragma unroll
        for (int i = tid; i < 4096; i += 256) {
            int r  = i >> 5;
            int c4 = (i & 31) << 2;
            float4 v = *(float4*)&smT[r * T_STRIDE + c4];
            *(float4*)&C[(size_t)(col0 + r) * NN + row0 + c4] = v;
        }
    }
}

// ---------------- GCN aggregation ----------------
template<int F, int RELU, int HAS_BIAS>
__global__ void __launch_bounds__(256) aggregate_kernel(
    const float* __restrict__ h, const float* __restrict__ bias,
    float* __restrict__ out)
{
    constexpr int VPT = F / 32;
    const int gw   = (blockIdx.x * 256 + threadIdx.x) >> 5;
    const int lane = threadIdx.x & 31;
    if (gw >= NN) return;

    float acc[VPT];
    const float di = g_deg_inv[gw];
    const float* hn = h + (size_t)gw * F;
#pragma unroll
    for (int i = 0; i < VPT; i++) {
        acc[i] = hn[(i << 5) + lane] * di;
        if (HAS_BIAS) acc[i] += bias[(i << 5) + lane];
    }

    int e = g_off[gw];
    const int e1 = g_off[gw + 1];
    for (; e + 1 < e1; e += 2) {
        int   s0 = g_csr_src[e],     s1 = g_csr_src[e + 1];
        float w0 = g_csr_norm[e],    w1 = g_csr_norm[e + 1];
        const float* p0 = h + (size_t)s0 * F;
        const float* p1 = h + (size_t)s1 * F;
#pragma unroll
        for (int i = 0; i < VPT; i++) acc[i] += p0[(i << 5) + lane] * w0;
#pragma unroll
        for (int i = 0; i < VPT; i++) acc[i] += p1[(i << 5) + lane] * w1;
    }
    if (e < e1) {
        int s = g_csr_src[e];
        float w = g_csr_norm[e];
        const float* p = h + (size_t)s * F;
#pragma unroll
        for (int i = 0; i < VPT; i++) acc[i] += p[(i << 5) + lane] * w;
    }
#pragma unroll
    for (int i = 0; i < VPT; i++) {
        float v = acc[i];
        if (RELU) v = fmaxf(v, 0.f);
        out[(size_t)gw * F + (i << 5) + lane] = v;
    }
}

// ---------------- launch ----------------
extern "C" void kernel_launch(void* const* d_in, const int* in_sizes, int n_in,
                              void* d_out, int out_size)
{
    const float* x    = (const float*)d_in[0];
    const int*   ei   = (const int*)d_in[1];     // int32 on device
    const float* W_e1 = (const float*)d_in[2];
    const float* b_e1 = (const float*)d_in[3];
    const float* W_e2 = (const float*)d_in[4];
    const float* b_e2 = (const float*)d_in[5];
    const float* W_a1 = (const float*)d_in[6];
    const float* b_a1 = (const float*)d_in[7];
    const float* W_a2 = (const float*)d_in[8];
    const float* b_a2 = (const float*)d_in[9];
    const float* W_s  = (const float*)d_in[10];
    const float* b_s  = (const float*)d_in[11];

    float* out   = (float*)d_out;
    float* x_hat = out;                                 // [NN, 256]
    float* a_hat = out + (size_t)NN * 256;              // [NN, NN]
    float* zout  = a_hat + (size_t)NN * NN;             // [NN, 64]

    float *p_tmp, *p_h1, *p_a;
    __half *p_shi, *p_smid;
    cudaGetSymbolAddress((void**)&p_tmp,  g_tmp);
    cudaGetSymbolAddress((void**)&p_h1,   g_h1);
    cudaGetSymbolAddress((void**)&p_a,    g_a);
    cudaGetSymbolAddress((void**)&p_shi,  g_s_hi);
    cudaGetSymbolAddress((void**)&p_smid, g_s_mid);

    const int gemm_smem = (128 + 128 + 64 + 64) * SM_STRIDE * 2;   // 55296 B
    const int syrk_smem = 4 * 128 * SM_STRIDE * 2;                 // 73728 B
    const int scan_smem = (NN + 32) * 4;                           // 49280 B

    static cudaStream_t s_side = nullptr;
    static cudaEvent_t  ev_fork, ev_l1, ev_zagg, ev_side_done;
    if (!s_side) {
        cudaStreamCreateWithFlags(&s_side, cudaStreamNonBlocking);
        cudaEventCreateWithFlags(&ev_fork,      cudaEventDisableTiming);
        cudaEventCreateWithFlags(&ev_l1,        cudaEventDisableTiming);
        cudaEventCreateWithFlags(&ev_zagg,      cudaEventDisableTiming);
        cudaEventCreateWithFlags(&ev_side_done, cudaEventDisableTiming);
        cudaFuncSetAttribute(gemm_mma_kernel<0,0,0>, cudaFuncAttributeMaxDynamicSharedMemorySize, gemm_smem);
        cudaFuncSetAttribute(gemm_mma_kernel<1,0,1>, cudaFuncAttributeMaxDynamicSharedMemorySize, gemm_smem);
        cudaFuncSetAttribute(gemm_mma_kernel<1,1,1>, cudaFuncAttributeMaxDynamicSharedMemorySize, gemm_smem);
        cudaFuncSetAttribute(gemm_mma_kernel<0,0,1>, cudaFuncAttributeMaxDynamicSharedMemorySize, gemm_smem);
        cudaFuncSetAttribute(syrk_mma_kernel, cudaFuncAttributeMaxDynamicSharedMemorySize, syrk_smem);
        cudaFuncSetAttribute(k_scan, cudaFuncAttributeMaxDynamicSharedMemorySize, scan_smem);
    }

    // ---- fork: side stream runs the encoder-L1 GEMM while main builds CSR ----
    cudaEventRecord(ev_fork, 0);
    cudaStreamWaitEvent(s_side, ev_fork, 0);

    gemm_mma_kernel<0,0,0><<<dim3(2, 96), 256, gemm_smem, s_side>>>(
        x, W_e1, nullptr, p_tmp, nullptr, nullptr, 256, 128);
    cudaEventRecord(ev_l1, s_side);

    // main: CSR build (int atomics only; 2 edges/thread)
    k_init <<<48,  256>>>();
    k_count<<<768, 256>>>(ei);
    k_scan <<<1,   1024, scan_smem>>>();
    k_fill <<<768, 256>>>(ei);

    cudaStreamWaitEvent(0, ev_l1, 0);
    aggregate_kernel<128, 1, 1><<<1536, 256>>>(p_tmp, b_e1, p_h1);

    gemm_mma_kernel<0,0,0><<<dim3(1, 96), 256, gemm_smem>>>(p_h1, W_e2, nullptr, p_tmp, nullptr, nullptr, 128, 64);
    aggregate_kernel<64, 1, 1><<<1536, 256>>>(p_tmp, b_e2, zout);

    // zagg = agg(z) (shared by both decoder branches; agg is linear)
    aggregate_kernel<64, 0, 0><<<1536, 256>>>(zout, nullptr, p_tmp);
    cudaEventRecord(ev_zagg, 0);

    // ---- main stream: structure branch (long pole): s GEMM -> syrk ----
    gemm_mma_kernel<1,1,1><<<dim3(1, 96), 256, gemm_smem>>>(p_tmp, W_s, b_s, nullptr, p_shi, p_smid, 64, 64);
    syrk_mma_kernel<<<dim3(96, 96), 256, syrk_smem>>>(p_shi, p_smid, a_hat);

    // ---- side stream: attribute branch (hidden under syrk) ----
    cudaStreamWaitEvent(s_side, ev_zagg, 0);
    gemm_mma_kernel<1,0,1><<<dim3(2, 96), 256, gemm_smem, s_side>>>(
        p_tmp, W_a1, b_a1, p_a, nullptr, nullptr, 64, 128);
    aggregate_kernel<128, 0, 0><<<1536, 256, 0, s_side>>>(p_a, nullptr, p_h1);
    gemm_mma_kernel<0,0,1><<<dim3(4, 96), 256, gemm_smem, s_side>>>(
        p_h1, W_a2, b_a2, x_hat, nullptr, nullptr, 128, 256);
    cudaEventRecord(ev_side_done, s_side);

    cudaStreamWaitEvent(0, ev_side_done, 0);
}